// round 7
// baseline (speedup 1.0000x reference)
#include <cuda_runtime.h>
#include <cuda_bf16.h>
#include <math.h>

// ---------------- problem constants ----------------
#define NTOK   8192
#define LSEQ   1024
#define D_IN   96
#define D_MID  192
#define DI     384
#define NST    16
#define RRANK  12
#define DBL_W  44

// ---------------- scratch ----------------
__device__ float g_xt [NTOK*D_IN];
__device__ float g_t1 [NTOK*D_IN];
__device__ float g_t2 [NTOK*D_MID];
__device__ float g_xz [NTOK*768];
__device__ float g_xc [NTOK*DI];
__device__ float g_dbl[NTOK*DBL_W];
__device__ float g_dt [NTOK*DI];
__device__ float g_y  [NTOK*DI];
__device__ float g_t3 [NTOK*D_MID];
__device__ float g_t4 [NTOK*D_MID];
__device__ float g_w1t[9*D_IN*D_IN];   // [tap][O][Cin]
__device__ float g_w4t[9*D_MID*D_MID]; // [tap][O][Cin]
__device__ float g_bns[768];
__device__ float g_bnb[768];
__device__ float g_A  [DI*NST];

// ---------------- activations ----------------
__device__ __forceinline__ float siluf(float x){ return x / (1.0f + __expf(-x)); }
__device__ __forceinline__ float geluf(float x){ return 0.5f*x*(1.0f + erff(x*0.70710678118654752f)); }
__device__ __forceinline__ float softplusf(float x){ return fmaxf(x,0.0f) + log1pf(__expf(-fabsf(x))); }
template<int ACT>
__device__ __forceinline__ float act_apply(float v){
  if (ACT==1) return geluf(v);
  if (ACT==2) return siluf(v);
  if (ACT==3) return softplusf(v);
  return v;
}

// ---------------- mma helpers ----------------
__device__ __forceinline__ void ldsm4(unsigned &r0, unsigned &r1, unsigned &r2, unsigned &r3, unsigned addr){
  asm volatile("ldmatrix.sync.aligned.m8n8.x4.shared.b16 {%0,%1,%2,%3}, [%4];"
    : "=r"(r0),"=r"(r1),"=r"(r2),"=r"(r3) : "r"(addr));
}
__device__ __forceinline__ void mma16816(float d[4], const unsigned a[4], unsigned b0, unsigned b1){
  asm volatile("mma.sync.aligned.m16n8k16.row.col.f32.bf16.bf16.f32 "
    "{%0,%1,%2,%3}, {%4,%5,%6,%7}, {%8,%9}, {%0,%1,%2,%3};"
    : "+f"(d[0]),"+f"(d[1]),"+f"(d[2]),"+f"(d[3])
    : "r"(a[0]),"r"(a[1]),"r"(a[2]),"r"(a[3]), "r"(b0),"r"(b1));
}
__device__ __forceinline__ void split_bf16(float x, __nv_bfloat16 &h, __nv_bfloat16 &l){
  h = __float2bfloat16_rn(x);
  l = __float2bfloat16_rn(x - __bfloat162float(h));
}

// ---------------- prep ----------------
__global__ void prep_kernel(const float* __restrict__ g1,const float* __restrict__ b1,
                            const float* __restrict__ m1,const float* __restrict__ v1,
                            const float* __restrict__ g2,const float* __restrict__ b2,
                            const float* __restrict__ m2,const float* __restrict__ v2,
                            const float* __restrict__ g3,const float* __restrict__ b3,
                            const float* __restrict__ m3,const float* __restrict__ v3,
                            const float* __restrict__ g4,const float* __restrict__ b4,
                            const float* __restrict__ m4,const float* __restrict__ v4,
                            const float* __restrict__ A_log)
{
  int i = blockIdx.x*256 + threadIdx.x;
  const float eps = 1e-5f;
  if (i < 96){  float s = g1[i]*rsqrtf(v1[i]+eps); g_bns[i]     = s; g_bnb[i]     = b1[i]-m1[i]*s; }
  if (i < 192){ float s = g2[i]*rsqrtf(v2[i]+eps); g_bns[192+i] = s; g_bnb[192+i] = b2[i]-m2[i]*s;
                      s = g3[i]*rsqrtf(v3[i]+eps); g_bns[384+i] = s; g_bnb[384+i] = b3[i]-m3[i]*s;
                      s = g4[i]*rsqrtf(v4[i]+eps); g_bns[576+i] = s; g_bnb[576+i] = b4[i]-m4[i]*s; }
  if (i < DI*NST) g_A[i] = -expf(A_log[i]);
}

// ---------------- transpose NCHW -> token-major ----------------
__global__ void transpose_in(const float* __restrict__ x, float* __restrict__ out)
{
  __shared__ float tile[32][33];
  int bc = blockIdx.x, bl = blockIdx.y, b = blockIdx.z;
  int tx = threadIdx.x, ty = threadIdx.y;
  #pragma unroll
  for (int i = ty; i < 32; i += 8)
    tile[i][tx] = x[(b*D_IN + bc*32 + i)*LSEQ + bl*32 + tx];
  __syncthreads();
  #pragma unroll
  for (int i = ty; i < 32; i += 8)
    out[(b*LSEQ + bl*32 + i)*D_IN + bc*32 + tx] = tile[tx][i];
}

// ---------------- weight transform: (O,C,3,3) -> (tap,O,Cin) ----------------
__global__ void transform_w(const float* __restrict__ w, float* __restrict__ wt, int O, int Cin)
{
  int idx = blockIdx.x*256 + threadIdx.x;
  int total = O*Cin*9;
  if (idx < total){
    int o = idx/(Cin*9); int r = idx - o*(Cin*9); int c = r/9; int t = r - c*9;
    wt[((size_t)(t*O + o))*Cin + c] = w[idx];
  }
}

// ---------------- tile config ----------------
#define BM 64
#define BN 64
#define BKT 16
#define BKP 24   // padded bf16 row stride (48B) -> conflict-free ldmatrix

// =====================================================================
// bf16 split (3xMMA) NT GEMM. 128 threads, BM=BN=64, warps 2x2 (m32n32).
// C[i,j] = act( dot(A[i,:K], B[j,:K]) * scale[j] + shift[j] )
// =====================================================================
template<int ACT>
__global__ void __launch_bounds__(128)
gemm_nt(const float* __restrict__ A, int lda,
        const float* __restrict__ B,
        float* __restrict__ C,
        int N, int K,
        const float* __restrict__ scale, const float* __restrict__ shift)
{
  __shared__ __nv_bfloat16 Ah[BM][BKP], Al[BM][BKP], Bh[BN][BKP], Bl[BN][BKP];
  const int tid  = threadIdx.x;
  const int lane = tid & 31;
  const int warp = tid >> 5;
  const int row0 = blockIdx.x * BM;
  const int col0 = blockIdx.y * BN;
  const int wm = (warp >> 1) * 32;
  const int wn = (warp &  1) * 32;

  float d[2][4][4];
  #pragma unroll
  for (int i=0;i<2;i++)
    #pragma unroll
    for (int j=0;j<4;j++)
      { d[i][j][0]=0.f; d[i][j][1]=0.f; d[i][j][2]=0.f; d[i][j][3]=0.f; }

  const int ai = tid >> 1;
  const int ak = (tid & 1) * 8;
  const bool jv = (col0 + ai) < N;

  const unsigned aH = (unsigned)__cvta_generic_to_shared(&Ah[0][0]);
  const unsigned aL = (unsigned)__cvta_generic_to_shared(&Al[0][0]);
  const unsigned bH = (unsigned)__cvta_generic_to_shared(&Bh[0][0]);
  const unsigned bL = (unsigned)__cvta_generic_to_shared(&Bl[0][0]);
  const int lrow = lane & 15, lcol = (lane >> 4) * 8;
  const unsigned offA0 = (unsigned)(((wm +      lrow)*BKP + lcol)*2);
  const unsigned offA1 = (unsigned)(((wm + 16 + lrow)*BKP + lcol)*2);
  const unsigned offB0 = (unsigned)(((wn +      lrow)*BKP + lcol)*2);
  const unsigned offB1 = (unsigned)(((wn + 16 + lrow)*BKP + lcol)*2);

  for (int k0 = 0; k0 < K; k0 += BKT){
    float av[8], bv[8];
    const float* Ar = A + (size_t)(row0 + ai)*lda + k0 + ak;
    if (k0 + ak + 8 <= K){
      float4 v0 = *(const float4*)(Ar);
      float4 v1 = *(const float4*)(Ar + 4);
      av[0]=v0.x; av[1]=v0.y; av[2]=v0.z; av[3]=v0.w;
      av[4]=v1.x; av[5]=v1.y; av[6]=v1.z; av[7]=v1.w;
    } else {
      #pragma unroll
      for (int u=0;u<8;++u) av[u] = (k0+ak+u < K) ? Ar[u] : 0.f;
    }
    const float* Br = B + (size_t)(col0 + ai)*K + k0 + ak;
    if (jv && (k0 + ak + 8 <= K)){
      float4 v0 = *(const float4*)(Br);
      float4 v1 = *(const float4*)(Br + 4);
      bv[0]=v0.x; bv[1]=v0.y; bv[2]=v0.z; bv[3]=v0.w;
      bv[4]=v1.x; bv[5]=v1.y; bv[6]=v1.z; bv[7]=v1.w;
    } else {
      #pragma unroll
      for (int u=0;u<8;++u) bv[u] = (jv && (k0+ak+u < K)) ? Br[u] : 0.f;
    }
    __syncthreads();
    #pragma unroll
    for (int u=0;u<8;++u){
      split_bf16(av[u], Ah[ai][ak+u], Al[ai][ak+u]);
      split_bf16(bv[u], Bh[ai][ak+u], Bl[ai][ak+u]);
    }
    __syncthreads();

    unsigned ah[2][4], al[2][4], bh[2][4], bl[2][4];
    ldsm4(ah[0][0],ah[0][1],ah[0][2],ah[0][3], aH + offA0);
    ldsm4(ah[1][0],ah[1][1],ah[1][2],ah[1][3], aH + offA1);
    ldsm4(al[0][0],al[0][1],al[0][2],al[0][3], aL + offA0);
    ldsm4(al[1][0],al[1][1],al[1][2],al[1][3], aL + offA1);
    ldsm4(bh[0][0],bh[0][1],bh[0][2],bh[0][3], bH + offB0);
    ldsm4(bh[1][0],bh[1][1],bh[1][2],bh[1][3], bH + offB1);
    ldsm4(bl[0][0],bl[0][1],bl[0][2],bl[0][3], bL + offB0);
    ldsm4(bl[1][0],bl[1][1],bl[1][2],bl[1][3], bL + offB1);

    #pragma unroll
    for (int mf=0; mf<2; ++mf){
      #pragma unroll
      for (int nf=0; nf<4; ++nf){
        const int g = nf >> 1, s = nf & 1;
        mma16816(d[mf][nf], ah[mf], bh[g][s], bh[g][2+s]);
        mma16816(d[mf][nf], al[mf], bh[g][s], bh[g][2+s]);
        mma16816(d[mf][nf], ah[mf], bl[g][s], bl[g][2+s]);
      }
    }
  }

  // epilogue: c0,c1 -> (row=lane/4, col=(lane%4)*2 +0/1); c2,c3 -> row+8
  const int lr = lane >> 2;
  const int lc = (lane & 3) * 2;
  #pragma unroll
  for (int mf=0; mf<2; ++mf){
    #pragma unroll
    for (int nf=0; nf<4; ++nf){
      int gm = row0 + wm + mf*16 + lr;
      int gn = col0 + wn + nf*8 + lc;
      #pragma unroll
      for (int r=0; r<4; ++r){
        int m = gm + (r>>1)*8;
        int n = gn + (r&1);
        if (n < N){
          float sc = scale ? scale[n] : 1.f;
          float sb = shift ? shift[n] : 0.f;
          C[(size_t)m*N + n] = act_apply<ACT>(d[mf][nf][r]*sc + sb);
        }
      }
    }
  }
}

// =====================================================================
// 3x3 conv implicit GEMM (bf16 split 3xMMA). 9 shifted taps.
// X token-major (NTOK, Cin); Wt [tap][O][Cin] (k contiguous). Cin%16==0.
// =====================================================================
template<int ACT, bool NCHW_OUT>
__global__ void __launch_bounds__(128)
conv3x3_gemm(const float* __restrict__ X,
             const float* __restrict__ Wt,
             float* __restrict__ C,
             int Cin, int N,
             const float* __restrict__ scale, const float* __restrict__ shift)
{
  __shared__ __nv_bfloat16 Ah[BM][BKP], Al[BM][BKP], Bh[BN][BKP], Bl[BN][BKP];
  const int tid  = threadIdx.x;
  const int lane = tid & 31;
  const int warp = tid >> 5;
  const int row0 = blockIdx.x * BM;
  const int col0 = blockIdx.y * BN;
  const int wm = (warp >> 1) * 32;
  const int wn = (warp &  1) * 32;

  float d[2][4][4];
  #pragma unroll
  for (int i=0;i<2;i++)
    #pragma unroll
    for (int j=0;j<4;j++)
      { d[i][j][0]=0.f; d[i][j][1]=0.f; d[i][j][2]=0.f; d[i][j][3]=0.f; }

  const int ai = tid >> 1;
  const int ak = (tid & 1) * 8;
  const bool jv = (col0 + ai) < N;

  const int gt = row0 + ai;
  const int bb = gt >> 10;
  const int ll = gt & 1023;
  const int hh = ll >> 5, ww = ll & 31;

  const unsigned aH = (unsigned)__cvta_generic_to_shared(&Ah[0][0]);
  const unsigned aL = (unsigned)__cvta_generic_to_shared(&Al[0][0]);
  const unsigned bH = (unsigned)__cvta_generic_to_shared(&Bh[0][0]);
  const unsigned bL = (unsigned)__cvta_generic_to_shared(&Bl[0][0]);
  const int lrow = lane & 15, lcol = (lane >> 4) * 8;
  const unsigned offA0 = (unsigned)(((wm +      lrow)*BKP + lcol)*2);
  const unsigned offA1 = (unsigned)(((wm + 16 + lrow)*BKP + lcol)*2);
  const unsigned offB0 = (unsigned)(((wn +      lrow)*BKP + lcol)*2);
  const unsigned offB1 = (unsigned)(((wn + 16 + lrow)*BKP + lcol)*2);

  for (int tap = 0; tap < 9; ++tap){
    const int dy = tap/3 - 1, dx = tap - (tap/3)*3 - 1;
    const int nh = hh + dy, nw = ww + dx;
    const bool valid = ((unsigned)nh < 32u) && ((unsigned)nw < 32u);
    const float* src = X + (size_t)((bb<<10) + (nh<<5) + nw) * Cin;
    const float* wrow = Wt + ((size_t)(tap*N + col0 + ai))*Cin;

    for (int c0 = 0; c0 < Cin; c0 += BKT){
      float av[8], bv[8];
      if (valid){
        float4 v0 = *(const float4*)(src + c0 + ak);
        float4 v1 = *(const float4*)(src + c0 + ak + 4);
        av[0]=v0.x; av[1]=v0.y; av[2]=v0.z; av[3]=v0.w;
        av[4]=v1.x; av[5]=v1.y; av[6]=v1.z; av[7]=v1.w;
      } else {
        #pragma unroll
        for (int u=0;u<8;++u) av[u] = 0.f;
      }
      if (jv){
        float4 v0 = *(const float4*)(wrow + c0 + ak);
        float4 v1 = *(const float4*)(wrow + c0 + ak + 4);
        bv[0]=v0.x; bv[1]=v0.y; bv[2]=v0.z; bv[3]=v0.w;
        bv[4]=v1.x; bv[5]=v1.y; bv[6]=v1.z; bv[7]=v1.w;
      } else {
        #pragma unroll
        for (int u=0;u<8;++u) bv[u] = 0.f;
      }
      __syncthreads();
      #pragma unroll
      for (int u=0;u<8;++u){
        split_bf16(av[u], Ah[ai][ak+u], Al[ai][ak+u]);
        split_bf16(bv[u], Bh[ai][ak+u], Bl[ai][ak+u]);
      }
      __syncthreads();

      unsigned ah[2][4], al[2][4], bh[2][4], bl[2][4];
      ldsm4(ah[0][0],ah[0][1],ah[0][2],ah[0][3], aH + offA0);
      ldsm4(ah[1][0],ah[1][1],ah[1][2],ah[1][3], aH + offA1);
      ldsm4(al[0][0],al[0][1],al[0][2],al[0][3], aL + offA0);
      ldsm4(al[1][0],al[1][1],al[1][2],al[1][3], aL + offA1);
      ldsm4(bh[0][0],bh[0][1],bh[0][2],bh[0][3], bH + offB0);
      ldsm4(bh[1][0],bh[1][1],bh[1][2],bh[1][3], bH + offB1);
      ldsm4(bl[0][0],bl[0][1],bl[0][2],bl[0][3], bL + offB0);
      ldsm4(bl[1][0],bl[1][1],bl[1][2],bl[1][3], bL + offB1);

      #pragma unroll
      for (int mf=0; mf<2; ++mf){
        #pragma unroll
        for (int nf=0; nf<4; ++nf){
          const int g = nf >> 1, s = nf & 1;
          mma16816(d[mf][nf], ah[mf], bh[g][s], bh[g][2+s]);
          mma16816(d[mf][nf], al[mf], bh[g][s], bh[g][2+s]);
          mma16816(d[mf][nf], ah[mf], bl[g][s], bl[g][2+s]);
        }
      }
    }
  }

  const int lr = lane >> 2;
  const int lc = (lane & 3) * 2;
  #pragma unroll
  for (int mf=0; mf<2; ++mf){
    #pragma unroll
    for (int nf=0; nf<4; ++nf){
      int gm = row0 + wm + mf*16 + lr;
      int gn = col0 + wn + nf*8 + lc;
      #pragma unroll
      for (int r=0; r<4; ++r){
        int m = gm + (r>>1)*8;
        int n = gn + (r&1);
        if (n < N){
          float sc = scale ? scale[n] : 1.f;
          float sb = shift ? shift[n] : 0.f;
          float o = act_apply<ACT>(d[mf][nf][r]*sc + sb);
          if (NCHW_OUT){
            int ob = m >> 10, ol = m & 1023;
            C[(size_t)(ob*N + n)*LSEQ + ol] = o;
          } else {
            C[(size_t)m*N + n] = o;
          }
        }
      }
    }
  }
}

// ---------------- causal depthwise conv (K=4) + SiLU ----------------
__global__ void dwconv_silu(const float* __restrict__ cw, const float* __restrict__ cb)
{
  int idx = blockIdx.x*256 + threadIdx.x;
  if (idx >= NTOK*DI) return;
  int d = idx % DI;
  int tok = idx / DI;
  int b = tok >> 10, l = tok & 1023;
  float acc = cb[d];
  const float* xi = g_xz + (size_t)(b<<10)*768 + d;
  #pragma unroll
  for (int k=0;k<4;++k){
    int ll = l + k - 3;
    if (ll >= 0) acc = fmaf(xi[(size_t)ll*768], cw[d*4+k], acc);
  }
  g_xc[idx] = siluf(acc);
}

// ---------------- selective scan ----------------
__global__ void __launch_bounds__(128)
scan_kernel(const float* __restrict__ Dp)
{
  int gid = (blockIdx.x * 128 + threadIdx.x) >> 4;
  int n   = threadIdx.x & 15;
  int b   = gid / DI;
  int d   = gid - b*DI;
  float Aval = g_A[d*NST + n];
  float dpv  = Dp[d];
  float h = 0.f;
  const float* __restrict__ dtp = g_dt  + (size_t)(b<<10)*DI + d;
  const float* __restrict__ xcp = g_xc  + (size_t)(b<<10)*DI + d;
  const float* __restrict__ zp  = g_xz  + (size_t)(b<<10)*768 + 384 + d;
  const float* __restrict__ blp = g_dbl + (size_t)(b<<10)*DBL_W;
  float* __restrict__ yp = g_y + (size_t)(b<<10)*DI + d;

  #pragma unroll 4
  for (int l = 0; l < LSEQ; ++l){
    float dtv = dtp[(size_t)l*DI];
    float xcv = xcp[(size_t)l*DI];
    float Bv  = blp[(size_t)l*DBL_W + RRANK + n];
    float Cv  = blp[(size_t)l*DBL_W + RRANK + NST + n];
    float dA  = __expf(dtv * Aval);
    h = fmaf(dA, h, dtv*Bv*xcv);
    float p = h * Cv;
    p += __shfl_xor_sync(0xffffffffu, p, 8, 16);
    p += __shfl_xor_sync(0xffffffffu, p, 4, 16);
    p += __shfl_xor_sync(0xffffffffu, p, 2, 16);
    p += __shfl_xor_sync(0xffffffffu, p, 1, 16);
    if (n == 0){
      float zv = zp[(size_t)l*768];
      yp[(size_t)l*DI] = (p + xcv*dpv) * siluf(zv);
    }
  }
}

// ---------------- host launcher ----------------
extern "C" void kernel_launch(void* const* d_in, const int* in_sizes, int n_in,
                              void* d_out, int out_size)
{
  (void)in_sizes; (void)n_in; (void)out_size;
  const float* x    = (const float*)d_in[0];
  const float* w1   = (const float*)d_in[1];
  const float* g1   = (const float*)d_in[2];
  const float* b1   = (const float*)d_in[3];
  const float* m1   = (const float*)d_in[4];
  const float* v1   = (const float*)d_in[5];
  const float* w2   = (const float*)d_in[6];
  const float* g2   = (const float*)d_in[7];
  const float* b2   = (const float*)d_in[8];
  const float* m2   = (const float*)d_in[9];
  const float* v2   = (const float*)d_in[10];
  const float* in_w = (const float*)d_in[11];
  const float* cw   = (const float*)d_in[12];
  const float* cb   = (const float*)d_in[13];
  const float* xp_w = (const float*)d_in[14];
  const float* dt_w = (const float*)d_in[15];
  const float* dt_b = (const float*)d_in[16];
  const float* A_log= (const float*)d_in[17];
  const float* Dp   = (const float*)d_in[18];
  const float* out_w= (const float*)d_in[19];
  const float* w3   = (const float*)d_in[20];
  const float* g3   = (const float*)d_in[21];
  const float* b3   = (const float*)d_in[22];
  const float* m3   = (const float*)d_in[23];
  const float* v3   = (const float*)d_in[24];
  const float* w4   = (const float*)d_in[25];
  const float* g4   = (const float*)d_in[26];
  const float* b4   = (const float*)d_in[27];
  const float* m4   = (const float*)d_in[28];
  const float* v4   = (const float*)d_in[29];

  float *p_xt,*p_t1,*p_t2,*p_xz,*p_xc,*p_dbl,*p_dt,*p_y,*p_t3,*p_t4,*p_w1t,*p_w4t,*p_bns,*p_bnb;
  cudaGetSymbolAddress((void**)&p_xt , g_xt );
  cudaGetSymbolAddress((void**)&p_t1 , g_t1 );
  cudaGetSymbolAddress((void**)&p_t2 , g_t2 );
  cudaGetSymbolAddress((void**)&p_xz , g_xz );
  cudaGetSymbolAddress((void**)&p_xc , g_xc );
  cudaGetSymbolAddress((void**)&p_dbl, g_dbl);
  cudaGetSymbolAddress((void**)&p_dt , g_dt );
  cudaGetSymbolAddress((void**)&p_y  , g_y  );
  cudaGetSymbolAddress((void**)&p_t3 , g_t3 );
  cudaGetSymbolAddress((void**)&p_t4 , g_t4 );
  cudaGetSymbolAddress((void**)&p_w1t, g_w1t);
  cudaGetSymbolAddress((void**)&p_w4t, g_w4t);
  cudaGetSymbolAddress((void**)&p_bns, g_bns);
  cudaGetSymbolAddress((void**)&p_bnb, g_bnb);

  // conv1 stays at my 0-based launch #3 (ncu-captured slot)
  prep_kernel<<<24,256>>>(g1,b1,m1,v1, g2,b2,m2,v2, g3,b3,m3,v3, g4,b4,m4,v4, A_log);  // #0
  transpose_in<<<dim3(3,32,8), dim3(32,8)>>>(x, p_xt);                                  // #1
  transform_w<<<(D_IN*D_IN*9+255)/256,256>>>(w1, p_w1t, D_IN, D_IN);                    // #2
  conv3x3_gemm<1,false><<<dim3(NTOK/BM, 2),128>>>(p_xt, p_w1t, p_t1, D_IN, D_IN, p_bns+0, p_bnb+0); // #3
  transform_w<<<(D_MID*D_MID*9+255)/256,256>>>(w4, p_w4t, D_MID, D_MID);                // #4
  // conv2 1x1 + BN2 + SiLU
  gemm_nt<2><<<dim3(NTOK/BM, 3),128>>>(p_t1, D_IN, w2, p_t2, D_MID, D_IN, p_bns+192, p_bnb+192);
  // in_proj
  gemm_nt<0><<<dim3(NTOK/BM, 12),128>>>(p_t2, D_MID, in_w, p_xz, 768, D_MID, nullptr, nullptr);
  dwconv_silu<<<(NTOK*DI)/256,256>>>(cw, cb);
  // x_proj
  gemm_nt<0><<<dim3(NTOK/BM, 1),128>>>(p_xc, DI, xp_w, p_dbl, DBL_W, DI, nullptr, nullptr);
  // dt_proj + softplus
  gemm_nt<3><<<dim3(NTOK/BM, 6),128>>>(p_dbl, DBL_W, dt_w, p_dt, DI, RRANK, nullptr, dt_b);
  scan_kernel<<<(NTOK/LSEQ)*DI*16/128,128>>>(Dp);
  // out_proj
  gemm_nt<0><<<dim3(NTOK/BM, 3),128>>>(p_y, DI, out_w, p_t3, D_MID, DI, nullptr, nullptr);
  // conv3 1x1 + BN3 + SiLU
  gemm_nt<2><<<dim3(NTOK/BM, 3),128>>>(p_t3, D_MID, w3, p_t4, D_MID, D_MID, p_bns+384, p_bnb+384);
  // conv4 3x3 + BN4 + GELU -> NCHW
  conv3x3_gemm<1,true><<<dim3(NTOK/BM, 3),128>>>(p_t4, p_w4t, (float*)d_out, D_MID, D_MID, p_bns+576, p_bnb+576);
}

// round 8
// speedup vs baseline: 1.1167x; 1.1167x over previous
#include <cuda_runtime.h>
#include <cuda_bf16.h>
#include <math.h>

// ---------------- problem constants ----------------
#define NTOK   8192
#define LSEQ   1024
#define D_IN   96
#define D_MID  192
#define DI     384
#define NST    16
#define RRANK  12
#define DBL_W  44

// ---------------- packed bf16-pair format: u32 = hi | (lo<<16) ----------------
__device__ __forceinline__ unsigned packf(float x){
  __nv_bfloat16 h = __float2bfloat16_rn(x);
  float r = x - __bfloat162float(h);
  __nv_bfloat16 l = __float2bfloat16_rn(r);
  return (unsigned)__bfloat16_as_ushort(h) | ((unsigned)__bfloat16_as_ushort(l) << 16);
}
__device__ __forceinline__ float unpackf(unsigned p){
  __nv_bfloat16 h = __ushort_as_bfloat16((unsigned short)(p & 0xFFFF));
  __nv_bfloat16 l = __ushort_as_bfloat16((unsigned short)(p >> 16));
  return __bfloat162float(h) + __bfloat162float(l);
}
// unzip 8 packed pairs (2 x uint4) -> 8 hi bf16 (uint4) + 8 lo bf16 (uint4)
__device__ __forceinline__ void unzip8(uint4 p, uint4 q, uint4 &h, uint4 &l){
  h.x=__byte_perm(p.x,p.y,0x5410); h.y=__byte_perm(p.z,p.w,0x5410);
  h.z=__byte_perm(q.x,q.y,0x5410); h.w=__byte_perm(q.z,q.w,0x5410);
  l.x=__byte_perm(p.x,p.y,0x7632); l.y=__byte_perm(p.z,p.w,0x7632);
  l.z=__byte_perm(q.x,q.y,0x7632); l.w=__byte_perm(q.z,q.w,0x7632);
}

// ---------------- scratch ----------------
__device__ unsigned g_xt [NTOK*D_IN];     // packed activations
__device__ unsigned g_t1 [NTOK*D_IN];
__device__ unsigned g_t2 [NTOK*D_MID];
__device__ unsigned g_xz [NTOK*768];
__device__ unsigned g_xc [NTOK*DI];
__device__ unsigned g_y  [NTOK*DI];
__device__ unsigned g_t3 [NTOK*D_MID];
__device__ unsigned g_t4 [NTOK*D_MID];
__device__ float    g_dbl[NTOK*DBL_W];    // fp32 (scan consumes)
__device__ float    g_dt [NTOK*DI];
__device__ unsigned g_w1t[9*D_IN*D_IN];   // packed [tap][O][Cin]
__device__ unsigned g_w4t[9*D_MID*D_MID];
__device__ unsigned g_w2p[D_MID*D_IN];    // packed NT weights
__device__ unsigned g_inwp[768*D_MID];
__device__ unsigned g_xpwp[DBL_W*DI];
__device__ unsigned g_outwp[D_MID*DI];
__device__ unsigned g_w3p[D_MID*D_MID];
__device__ float    g_dtwT[RRANK*DI];     // dt_w transposed [r][d]
__device__ float    g_bns[768];
__device__ float    g_bnb[768];
__device__ float    g_A  [DI*NST];

// ---------------- activations ----------------
__device__ __forceinline__ float siluf(float x){ return x / (1.0f + __expf(-x)); }
__device__ __forceinline__ float geluf(float x){ return 0.5f*x*(1.0f + erff(x*0.70710678118654752f)); }
__device__ __forceinline__ float softplusf(float x){ return fmaxf(x,0.0f) + log1pf(__expf(-fabsf(x))); }
template<int ACT>
__device__ __forceinline__ float act_apply(float v){
  if (ACT==1) return geluf(v);
  if (ACT==2) return siluf(v);
  return v;
}

// ---------------- mma helpers ----------------
__device__ __forceinline__ void ldsm4(unsigned &r0, unsigned &r1, unsigned &r2, unsigned &r3, unsigned addr){
  asm volatile("ldmatrix.sync.aligned.m8n8.x4.shared.b16 {%0,%1,%2,%3}, [%4];"
    : "=r"(r0),"=r"(r1),"=r"(r2),"=r"(r3) : "r"(addr));
}
__device__ __forceinline__ void mma16816(float d[4], const unsigned a[4], unsigned b0, unsigned b1){
  asm volatile("mma.sync.aligned.m16n8k16.row.col.f32.bf16.bf16.f32 "
    "{%0,%1,%2,%3}, {%4,%5,%6,%7}, {%8,%9}, {%0,%1,%2,%3};"
    : "+f"(d[0]),"+f"(d[1]),"+f"(d[2]),"+f"(d[3])
    : "r"(a[0]),"r"(a[1]),"r"(a[2]),"r"(a[3]), "r"(b0),"r"(b1));
}

// ---------------- prep ----------------
__global__ void prep_kernel(const float* __restrict__ g1,const float* __restrict__ b1,
                            const float* __restrict__ m1,const float* __restrict__ v1,
                            const float* __restrict__ g2,const float* __restrict__ b2,
                            const float* __restrict__ m2,const float* __restrict__ v2,
                            const float* __restrict__ g3,const float* __restrict__ b3,
                            const float* __restrict__ m3,const float* __restrict__ v3,
                            const float* __restrict__ g4,const float* __restrict__ b4,
                            const float* __restrict__ m4,const float* __restrict__ v4,
                            const float* __restrict__ A_log, const float* __restrict__ dt_w)
{
  int i = blockIdx.x*256 + threadIdx.x;
  const float eps = 1e-5f;
  if (i < 96){  float s = g1[i]*rsqrtf(v1[i]+eps); g_bns[i]     = s; g_bnb[i]     = b1[i]-m1[i]*s; }
  if (i < 192){ float s = g2[i]*rsqrtf(v2[i]+eps); g_bns[192+i] = s; g_bnb[192+i] = b2[i]-m2[i]*s;
                      s = g3[i]*rsqrtf(v3[i]+eps); g_bns[384+i] = s; g_bnb[384+i] = b3[i]-m3[i]*s;
                      s = g4[i]*rsqrtf(v4[i]+eps); g_bns[576+i] = s; g_bnb[576+i] = b4[i]-m4[i]*s; }
  if (i < DI*NST) g_A[i] = -expf(A_log[i]);
  if (i < DI*RRANK){ int d = i/RRANK, r = i - d*RRANK; g_dtwT[r*DI + d] = dt_w[i]; }
}

// ---------------- pack fp32 -> packed pair ----------------
__global__ void pack_arr(const float* __restrict__ src, unsigned* __restrict__ dst, int n)
{
  int i = blockIdx.x*256 + threadIdx.x;
  if (i < n) dst[i] = packf(src[i]);
}

// ---------------- transpose NCHW -> token-major (packed) ----------------
__global__ void transpose_in(const float* __restrict__ x, unsigned* __restrict__ out)
{
  __shared__ float tile[32][33];
  int bc = blockIdx.x, bl = blockIdx.y, b = blockIdx.z;
  int tx = threadIdx.x, ty = threadIdx.y;
  #pragma unroll
  for (int i = ty; i < 32; i += 8)
    tile[i][tx] = x[(b*D_IN + bc*32 + i)*LSEQ + bl*32 + tx];
  __syncthreads();
  #pragma unroll
  for (int i = ty; i < 32; i += 8)
    out[(b*LSEQ + bl*32 + i)*D_IN + bc*32 + tx] = packf(tile[tx][i]);
}

// ---------------- weight transform: (O,C,3,3) -> packed (tap,O,Cin) ----------------
__global__ void transform_w(const float* __restrict__ w, unsigned* __restrict__ wt, int O, int Cin)
{
  int idx = blockIdx.x*256 + threadIdx.x;
  int total = O*Cin*9;
  if (idx < total){
    int o = idx/(Cin*9); int r = idx - o*(Cin*9); int c = r/9; int t = r - c*9;
    wt[((size_t)(t*O + o))*Cin + c] = packf(w[idx]);
  }
}

// ---------------- tile config ----------------
#define BM 64
#define BN 64
#define BKC 32   // k per chunk
#define BKP 40   // smem row stride (bf16 elems): 80B = 5x16B, conflict-light

// =====================================================================
// Packed-bf16-pair NT GEMM (3xMMA split). 128 threads, BM=BN=64.
// =====================================================================
template<int ACT, bool OUTP>
__global__ void __launch_bounds__(128)
gemm_nt(const unsigned* __restrict__ A, int lda,
        const unsigned* __restrict__ B,
        void* __restrict__ Cv,
        int N, int K,
        const float* __restrict__ scale, const float* __restrict__ shift)
{
  __shared__ __align__(16) unsigned short Ah[BM][BKP], Al[BM][BKP], Bh[BN][BKP], Bl[BN][BKP];
  const int tid  = threadIdx.x;
  const int lane = tid & 31;
  const int warp = tid >> 5;
  const int row0 = blockIdx.x * BM;
  const int col0 = blockIdx.y * BN;
  const int wm = (warp >> 1) * 32;
  const int wn = (warp &  1) * 32;

  float d[2][4][4];
  #pragma unroll
  for (int i=0;i<2;i++)
    #pragma unroll
    for (int j=0;j<4;j++)
      { d[i][j][0]=0.f; d[i][j][1]=0.f; d[i][j][2]=0.f; d[i][j][3]=0.f; }

  const int ai = tid >> 1;          // 0..63
  const int ak = (tid & 1) * 16;    // 0 or 16
  const bool jv = (col0 + ai) < N;

  const unsigned aH = (unsigned)__cvta_generic_to_shared(&Ah[0][0]);
  const unsigned aL = (unsigned)__cvta_generic_to_shared(&Al[0][0]);
  const unsigned bH = (unsigned)__cvta_generic_to_shared(&Bh[0][0]);
  const unsigned bL = (unsigned)__cvta_generic_to_shared(&Bl[0][0]);
  const int lrow = lane & 15, lcol = (lane >> 4) * 8;

  for (int k0 = 0; k0 < K; k0 += BKC){
    uint4 pa0,pa1,pa2,pa3, pb0,pb1,pb2,pb3;
    const uint4* Ap = (const uint4*)(A + (size_t)(row0 + ai)*lda + k0 + ak);
    pa0=Ap[0]; pa1=Ap[1]; pa2=Ap[2]; pa3=Ap[3];
    if (jv){
      const uint4* Bp = (const uint4*)(B + (size_t)(col0 + ai)*K + k0 + ak);
      pb0=Bp[0]; pb1=Bp[1]; pb2=Bp[2]; pb3=Bp[3];
    } else {
      pb0=make_uint4(0,0,0,0); pb1=pb0; pb2=pb0; pb3=pb0;
    }
    __syncthreads();
    {
      uint4 h,l;
      unzip8(pa0,pa1,h,l);
      *(uint4*)&Ah[ai][ak]   = h;  *(uint4*)&Al[ai][ak]   = l;
      unzip8(pa2,pa3,h,l);
      *(uint4*)&Ah[ai][ak+8] = h;  *(uint4*)&Al[ai][ak+8] = l;
      unzip8(pb0,pb1,h,l);
      *(uint4*)&Bh[ai][ak]   = h;  *(uint4*)&Bl[ai][ak]   = l;
      unzip8(pb2,pb3,h,l);
      *(uint4*)&Bh[ai][ak+8] = h;  *(uint4*)&Bl[ai][ak+8] = l;
    }
    __syncthreads();

    #pragma unroll
    for (int ks = 0; ks < BKC; ks += 16){
      unsigned ah[2][4], al[2][4], bh[2][4], bl[2][4];
      const unsigned oA0 = (unsigned)(((wm +      lrow)*BKP + ks + lcol)*2);
      const unsigned oA1 = (unsigned)(((wm + 16 + lrow)*BKP + ks + lcol)*2);
      const unsigned oB0 = (unsigned)(((wn +      lrow)*BKP + ks + lcol)*2);
      const unsigned oB1 = (unsigned)(((wn + 16 + lrow)*BKP + ks + lcol)*2);
      ldsm4(ah[0][0],ah[0][1],ah[0][2],ah[0][3], aH + oA0);
      ldsm4(ah[1][0],ah[1][1],ah[1][2],ah[1][3], aH + oA1);
      ldsm4(al[0][0],al[0][1],al[0][2],al[0][3], aL + oA0);
      ldsm4(al[1][0],al[1][1],al[1][2],al[1][3], aL + oA1);
      ldsm4(bh[0][0],bh[0][1],bh[0][2],bh[0][3], bH + oB0);
      ldsm4(bh[1][0],bh[1][1],bh[1][2],bh[1][3], bH + oB1);
      ldsm4(bl[0][0],bl[0][1],bl[0][2],bl[0][3], bL + oB0);
      ldsm4(bl[1][0],bl[1][1],bl[1][2],bl[1][3], bL + oB1);
      #pragma unroll
      for (int mf=0; mf<2; ++mf){
        #pragma unroll
        for (int nf=0; nf<4; ++nf){
          const int g = nf >> 1, s = nf & 1;
          mma16816(d[mf][nf], ah[mf], bh[g][s], bh[g][2+s]);
          mma16816(d[mf][nf], al[mf], bh[g][s], bh[g][2+s]);
          mma16816(d[mf][nf], ah[mf], bl[g][s], bl[g][2+s]);
        }
      }
    }
  }

  const int lr = lane >> 2;
  const int lc = (lane & 3) * 2;
  #pragma unroll
  for (int mf=0; mf<2; ++mf){
    #pragma unroll
    for (int nf=0; nf<4; ++nf){
      int gm = row0 + wm + mf*16 + lr;
      int gn = col0 + wn + nf*8 + lc;
      #pragma unroll
      for (int r=0; r<4; ++r){
        int m = gm + (r>>1)*8;
        int n = gn + (r&1);
        if (n < N){
          float sc = scale ? scale[n] : 1.f;
          float sb = shift ? shift[n] : 0.f;
          float o = act_apply<ACT>(d[mf][nf][r]*sc + sb);
          if (OUTP) ((unsigned*)Cv)[(size_t)m*N + n] = packf(o);
          else      ((float*)Cv)  [(size_t)m*N + n] = o;
        }
      }
    }
  }
}

// =====================================================================
// 3x3 conv implicit GEMM, packed pairs. Wt packed [tap][O][Cin].
// =====================================================================
template<int ACT, bool NCHW_OUT>
__global__ void __launch_bounds__(128)
conv3x3_gemm(const unsigned* __restrict__ X,
             const unsigned* __restrict__ Wt,
             void* __restrict__ Cv,
             int Cin, int N,
             const float* __restrict__ scale, const float* __restrict__ shift)
{
  __shared__ __align__(16) unsigned short Ah[BM][BKP], Al[BM][BKP], Bh[BN][BKP], Bl[BN][BKP];
  const int tid  = threadIdx.x;
  const int lane = tid & 31;
  const int warp = tid >> 5;
  const int row0 = blockIdx.x * BM;
  const int col0 = blockIdx.y * BN;
  const int wm = (warp >> 1) * 32;
  const int wn = (warp &  1) * 32;

  float d[2][4][4];
  #pragma unroll
  for (int i=0;i<2;i++)
    #pragma unroll
    for (int j=0;j<4;j++)
      { d[i][j][0]=0.f; d[i][j][1]=0.f; d[i][j][2]=0.f; d[i][j][3]=0.f; }

  const int ai = tid >> 1;
  const int ak = (tid & 1) * 16;
  const bool jv = (col0 + ai) < N;

  const int gt = row0 + ai;
  const int bb = gt >> 10;
  const int ll = gt & 1023;
  const int hh = ll >> 5, ww = ll & 31;

  const unsigned aH = (unsigned)__cvta_generic_to_shared(&Ah[0][0]);
  const unsigned aL = (unsigned)__cvta_generic_to_shared(&Al[0][0]);
  const unsigned bH = (unsigned)__cvta_generic_to_shared(&Bh[0][0]);
  const unsigned bL = (unsigned)__cvta_generic_to_shared(&Bl[0][0]);
  const int lrow = lane & 15, lcol = (lane >> 4) * 8;

  for (int tap = 0; tap < 9; ++tap){
    const int dy = tap/3 - 1, dx = tap - (tap/3)*3 - 1;
    const int nh = hh + dy, nw = ww + dx;
    const bool valid = ((unsigned)nh < 32u) && ((unsigned)nw < 32u);
    const unsigned* src  = X + (size_t)((bb<<10) + (nh<<5) + nw) * Cin;
    const unsigned* wrow = Wt + ((size_t)(tap*N + col0 + ai))*Cin;

    for (int c0 = 0; c0 < Cin; c0 += BKC){
      uint4 pa0,pa1,pa2,pa3, pb0,pb1,pb2,pb3;
      if (valid){
        const uint4* Ap = (const uint4*)(src + c0 + ak);
        pa0=Ap[0]; pa1=Ap[1]; pa2=Ap[2]; pa3=Ap[3];
      } else {
        pa0=make_uint4(0,0,0,0); pa1=pa0; pa2=pa0; pa3=pa0;
      }
      if (jv){
        const uint4* Bp = (const uint4*)(wrow + c0 + ak);
        pb0=Bp[0]; pb1=Bp[1]; pb2=Bp[2]; pb3=Bp[3];
      } else {
        pb0=make_uint4(0,0,0,0); pb1=pb0; pb2=pb0; pb3=pb0;
      }
      __syncthreads();
      {
        uint4 h,l;
        unzip8(pa0,pa1,h,l);
        *(uint4*)&Ah[ai][ak]   = h;  *(uint4*)&Al[ai][ak]   = l;
        unzip8(pa2,pa3,h,l);
        *(uint4*)&Ah[ai][ak+8] = h;  *(uint4*)&Al[ai][ak+8] = l;
        unzip8(pb0,pb1,h,l);
        *(uint4*)&Bh[ai][ak]   = h;  *(uint4*)&Bl[ai][ak]   = l;
        unzip8(pb2,pb3,h,l);
        *(uint4*)&Bh[ai][ak+8] = h;  *(uint4*)&Bl[ai][ak+8] = l;
      }
      __syncthreads();

      #pragma unroll
      for (int ks = 0; ks < BKC; ks += 16){
        unsigned ah[2][4], al[2][4], bh[2][4], bl[2][4];
        const unsigned oA0 = (unsigned)(((wm +      lrow)*BKP + ks + lcol)*2);
        const unsigned oA1 = (unsigned)(((wm + 16 + lrow)*BKP + ks + lcol)*2);
        const unsigned oB0 = (unsigned)(((wn +      lrow)*BKP + ks + lcol)*2);
        const unsigned oB1 = (unsigned)(((wn + 16 + lrow)*BKP + ks + lcol)*2);
        ldsm4(ah[0][0],ah[0][1],ah[0][2],ah[0][3], aH + oA0);
        ldsm4(ah[1][0],ah[1][1],ah[1][2],ah[1][3], aH + oA1);
        ldsm4(al[0][0],al[0][1],al[0][2],al[0][3], aL + oA0);
        ldsm4(al[1][0],al[1][1],al[1][2],al[1][3], aL + oA1);
        ldsm4(bh[0][0],bh[0][1],bh[0][2],bh[0][3], bH + oB0);
        ldsm4(bh[1][0],bh[1][1],bh[1][2],bh[1][3], bH + oB1);
        ldsm4(bl[0][0],bl[0][1],bl[0][2],bl[0][3], bL + oB0);
        ldsm4(bl[1][0],bl[1][1],bl[1][2],bl[1][3], bL + oB1);
        #pragma unroll
        for (int mf=0; mf<2; ++mf){
          #pragma unroll
          for (int nf=0; nf<4; ++nf){
            const int g = nf >> 1, s = nf & 1;
            mma16816(d[mf][nf], ah[mf], bh[g][s], bh[g][2+s]);
            mma16816(d[mf][nf], al[mf], bh[g][s], bh[g][2+s]);
            mma16816(d[mf][nf], ah[mf], bl[g][s], bl[g][2+s]);
          }
        }
      }
    }
  }

  const int lr = lane >> 2;
  const int lc = (lane & 3) * 2;
  #pragma unroll
  for (int mf=0; mf<2; ++mf){
    #pragma unroll
    for (int nf=0; nf<4; ++nf){
      int gm = row0 + wm + mf*16 + lr;
      int gn = col0 + wn + nf*8 + lc;
      #pragma unroll
      for (int r=0; r<4; ++r){
        int m = gm + (r>>1)*8;
        int n = gn + (r&1);
        if (n < N){
          float sc = scale ? scale[n] : 1.f;
          float sb = shift ? shift[n] : 0.f;
          float o = act_apply<ACT>(d[mf][nf][r]*sc + sb);
          if (NCHW_OUT){
            int ob = m >> 10, ol = m & 1023;
            ((float*)Cv)[(size_t)(ob*N + n)*LSEQ + ol] = o;
          } else {
            ((unsigned*)Cv)[(size_t)m*N + n] = packf(o);
          }
        }
      }
    }
  }
}

// ---------------- causal depthwise conv (K=4) + SiLU ----------------
__global__ void dwconv_silu(const float* __restrict__ cw, const float* __restrict__ cb)
{
  int idx = blockIdx.x*256 + threadIdx.x;
  if (idx >= NTOK*DI) return;
  int d = idx % DI;
  int tok = idx / DI;
  int b = tok >> 10, l = tok & 1023;
  float acc = cb[d];
  const unsigned* xi = g_xz + (size_t)(b<<10)*768 + d;
  #pragma unroll
  for (int k=0;k<4;++k){
    int ll = l + k - 3;
    if (ll >= 0) acc = fmaf(unpackf(xi[(size_t)ll*768]), cw[d*4+k], acc);
  }
  g_xc[idx] = packf(siluf(acc));
}

// ---------------- dt-proj (K=12) + softplus, SIMT ----------------
__global__ void dtproj_kernel(const float* __restrict__ dt_b)
{
  int idx = blockIdx.x*256 + threadIdx.x;
  if (idx >= NTOK*DI) return;
  int d = idx % DI;
  int t = idx / DI;
  const float* row = g_dbl + (size_t)t*DBL_W;
  float acc = dt_b[d];
  #pragma unroll
  for (int r=0;r<RRANK;++r)
    acc = fmaf(__ldg(row + r), g_dtwT[r*DI + d], acc);
  g_dt[idx] = softplusf(acc);
}

// ---------------- selective scan ----------------
__global__ void __launch_bounds__(128)
scan_kernel(const float* __restrict__ Dp)
{
  int gid = (blockIdx.x * 128 + threadIdx.x) >> 4;
  int n   = threadIdx.x & 15;
  int b   = gid / DI;
  int d   = gid - b*DI;
  float Aval = g_A[d*NST + n];
  float dpv  = Dp[d];
  float h = 0.f;
  const float*    __restrict__ dtp = g_dt  + (size_t)(b<<10)*DI + d;
  const unsigned* __restrict__ xcp = g_xc  + (size_t)(b<<10)*DI + d;
  const unsigned* __restrict__ zp  = g_xz  + (size_t)(b<<10)*768 + 384 + d;
  const float*    __restrict__ blp = g_dbl + (size_t)(b<<10)*DBL_W;
  unsigned* __restrict__ yp = g_y + (size_t)(b<<10)*DI + d;

  #pragma unroll 4
  for (int l = 0; l < LSEQ; ++l){
    float dtv = dtp[(size_t)l*DI];
    float xcv = unpackf(xcp[(size_t)l*DI]);
    float Bv  = blp[(size_t)l*DBL_W + RRANK + n];
    float Cv  = blp[(size_t)l*DBL_W + RRANK + NST + n];
    float dA  = __expf(dtv * Aval);
    h = fmaf(dA, h, dtv*Bv*xcv);
    float p = h * Cv;
    p += __shfl_xor_sync(0xffffffffu, p, 8, 16);
    p += __shfl_xor_sync(0xffffffffu, p, 4, 16);
    p += __shfl_xor_sync(0xffffffffu, p, 2, 16);
    p += __shfl_xor_sync(0xffffffffu, p, 1, 16);
    if (n == 0){
      float zv = unpackf(zp[(size_t)l*768]);
      yp[(size_t)l*DI] = packf((p + xcv*dpv) * siluf(zv));
    }
  }
}

// ---------------- host launcher ----------------
extern "C" void kernel_launch(void* const* d_in, const int* in_sizes, int n_in,
                              void* d_out, int out_size)
{
  (void)in_sizes; (void)n_in; (void)out_size;
  const float* x    = (const float*)d_in[0];
  const float* w1   = (const float*)d_in[1];
  const float* g1   = (const float*)d_in[2];
  const float* b1   = (const float*)d_in[3];
  const float* m1   = (const float*)d_in[4];
  const float* v1   = (const float*)d_in[5];
  const float* w2   = (const float*)d_in[6];
  const float* g2   = (const float*)d_in[7];
  const float* b2   = (const float*)d_in[8];
  const float* m2   = (const float*)d_in[9];
  const float* v2   = (const float*)d_in[10];
  const float* in_w = (const float*)d_in[11];
  const float* cw   = (const float*)d_in[12];
  const float* cb   = (const float*)d_in[13];
  const float* xp_w = (const float*)d_in[14];
  const float* dt_w = (const float*)d_in[15];
  const float* dt_b = (const float*)d_in[16];
  const float* A_log= (const float*)d_in[17];
  const float* Dp   = (const float*)d_in[18];
  const float* out_w= (const float*)d_in[19];
  const float* w3   = (const float*)d_in[20];
  const float* g3   = (const float*)d_in[21];
  const float* b3   = (const float*)d_in[22];
  const float* m3   = (const float*)d_in[23];
  const float* v3   = (const float*)d_in[24];
  const float* w4   = (const float*)d_in[25];
  const float* g4   = (const float*)d_in[26];
  const float* b4   = (const float*)d_in[27];
  const float* m4   = (const float*)d_in[28];
  const float* v4   = (const float*)d_in[29];

  unsigned *p_xt,*p_t1,*p_t2,*p_xz,*p_xc,*p_y,*p_t3,*p_t4,*p_w1t,*p_w4t;
  unsigned *p_w2p,*p_inwp,*p_xpwp,*p_outwp,*p_w3p;
  float *p_dbl,*p_bns,*p_bnb;
  cudaGetSymbolAddress((void**)&p_xt , g_xt );
  cudaGetSymbolAddress((void**)&p_t1 , g_t1 );
  cudaGetSymbolAddress((void**)&p_t2 , g_t2 );
  cudaGetSymbolAddress((void**)&p_xz , g_xz );
  cudaGetSymbolAddress((void**)&p_xc , g_xc );
  cudaGetSymbolAddress((void**)&p_y  , g_y  );
  cudaGetSymbolAddress((void**)&p_t3 , g_t3 );
  cudaGetSymbolAddress((void**)&p_t4 , g_t4 );
  cudaGetSymbolAddress((void**)&p_w1t, g_w1t);
  cudaGetSymbolAddress((void**)&p_w4t, g_w4t);
  cudaGetSymbolAddress((void**)&p_w2p, g_w2p);
  cudaGetSymbolAddress((void**)&p_inwp, g_inwp);
  cudaGetSymbolAddress((void**)&p_xpwp, g_xpwp);
  cudaGetSymbolAddress((void**)&p_outwp, g_outwp);
  cudaGetSymbolAddress((void**)&p_w3p, g_w3p);
  cudaGetSymbolAddress((void**)&p_dbl, g_dbl);
  cudaGetSymbolAddress((void**)&p_bns, g_bns);
  cudaGetSymbolAddress((void**)&p_bnb, g_bnb);

  // conv1 at my 0-based launch #3 (ncu-captured slot)
  prep_kernel<<<24,256>>>(g1,b1,m1,v1, g2,b2,m2,v2, g3,b3,m3,v3, g4,b4,m4,v4, A_log, dt_w); // #0
  transpose_in<<<dim3(3,32,8), dim3(32,8)>>>(x, p_xt);                                       // #1
  transform_w<<<(D_IN*D_IN*9+255)/256,256>>>(w1, p_w1t, D_IN, D_IN);                         // #2
  conv3x3_gemm<1,false><<<dim3(NTOK/BM, 2),128>>>(p_xt, p_w1t, p_t1, D_IN, D_IN, p_bns+0, p_bnb+0); // #3
  transform_w<<<(D_MID*D_MID*9+255)/256,256>>>(w4, p_w4t, D_MID, D_MID);                     // #4
  pack_arr<<<(D_MID*D_IN+255)/256,256>>>(w2, p_w2p, D_MID*D_IN);
  pack_arr<<<(768*D_MID+255)/256,256>>>(in_w, p_inwp, 768*D_MID);
  pack_arr<<<(DBL_W*DI+255)/256,256>>>(xp_w, p_xpwp, DBL_W*DI);
  pack_arr<<<(D_MID*DI+255)/256,256>>>(out_w, p_outwp, D_MID*DI);
  pack_arr<<<(D_MID*D_MID+255)/256,256>>>(w3, p_w3p, D_MID*D_MID);

  // conv2 1x1 + BN2 + SiLU
  gemm_nt<2,true><<<dim3(NTOK/BM, 3),128>>>(p_t1, D_IN, p_w2p, p_t2, D_MID, D_IN, p_bns+192, p_bnb+192);
  // in_proj
  gemm_nt<0,true><<<dim3(NTOK/BM, 12),128>>>(p_t2, D_MID, p_inwp, p_xz, 768, D_MID, nullptr, nullptr);
  dwconv_silu<<<(NTOK*DI)/256,256>>>(cw, cb);
  // x_proj -> fp32 g_dbl
  gemm_nt<0,false><<<dim3(NTOK/BM, 1),128>>>(p_xc, DI, p_xpwp, p_dbl, DBL_W, DI, nullptr, nullptr);
  // dt-proj + softplus (SIMT)
  dtproj_kernel<<<(NTOK*DI)/256,256>>>(dt_b);
  scan_kernel<<<(NTOK/LSEQ)*DI*16/128,128>>>(Dp);
  // out_proj
  gemm_nt<0,true><<<dim3(NTOK/BM, 3),128>>>(p_y, DI, p_outwp, p_t3, D_MID, DI, nullptr, nullptr);
  // conv3 1x1 + BN3 + SiLU
  gemm_nt<2,true><<<dim3(NTOK/BM, 3),128>>>(p_t3, D_MID, p_w3p, p_t4, D_MID, D_MID, p_bns+384, p_bnb+384);
  // conv4 3x3 + BN4 + GELU -> NCHW fp32
  conv3x3_gemm<1,true><<<dim3(NTOK/BM, 3),128>>>(p_t4, p_w4t, (float*)d_out, D_MID, D_MID, p_bns+576, p_bnb+576);
}

// round 9
// speedup vs baseline: 1.1675x; 1.0455x over previous
#include <cuda_runtime.h>
#include <cuda_bf16.h>
#include <math.h>

// ---------------- problem constants ----------------
#define NTOK   8192
#define LSEQ   1024
#define D_IN   96
#define D_MID  192
#define DI     384
#define NST    16
#define RRANK  12
#define DBL_W  44

// ---------------- packed bf16-pair format: u32 = hi | (lo<<16) ----------------
__device__ __forceinline__ unsigned packf(float x){
  __nv_bfloat16 h = __float2bfloat16_rn(x);
  float r = x - __bfloat162float(h);
  __nv_bfloat16 l = __float2bfloat16_rn(r);
  return (unsigned)__bfloat16_as_ushort(h) | ((unsigned)__bfloat16_as_ushort(l) << 16);
}
__device__ __forceinline__ float unpackf(unsigned p){
  __nv_bfloat16 h = __ushort_as_bfloat16((unsigned short)(p & 0xFFFF));
  __nv_bfloat16 l = __ushort_as_bfloat16((unsigned short)(p >> 16));
  return __bfloat162float(h) + __bfloat162float(l);
}
__device__ __forceinline__ void unzip8(uint4 p, uint4 q, uint4 &h, uint4 &l){
  h.x=__byte_perm(p.x,p.y,0x5410); h.y=__byte_perm(p.z,p.w,0x5410);
  h.z=__byte_perm(q.x,q.y,0x5410); h.w=__byte_perm(q.z,q.w,0x5410);
  l.x=__byte_perm(p.x,p.y,0x7632); l.y=__byte_perm(p.z,p.w,0x7632);
  l.z=__byte_perm(q.x,q.y,0x7632); l.w=__byte_perm(q.z,q.w,0x7632);
}

// ---------------- scratch ----------------
__device__ unsigned g_xt [NTOK*D_IN];
__device__ unsigned g_t1 [NTOK*D_IN];
__device__ unsigned g_t2 [NTOK*D_MID];
__device__ unsigned g_xz [NTOK*768];
__device__ unsigned g_xc [NTOK*DI];
__device__ unsigned g_y  [NTOK*DI];
__device__ unsigned g_t3 [NTOK*D_MID];
__device__ unsigned g_t4 [NTOK*D_MID];
__device__ float    g_dbl[NTOK*DBL_W];
__device__ float    g_dt [NTOK*DI];
__device__ unsigned g_w1t[9*D_IN*D_IN];
__device__ unsigned g_w4t[9*D_MID*D_MID];
__device__ unsigned g_w2p[D_MID*D_IN];
__device__ unsigned g_inwp[768*D_MID];
__device__ unsigned g_xpwp[DBL_W*DI];
__device__ unsigned g_outwp[D_MID*DI];
__device__ unsigned g_w3p[D_MID*D_MID];
__device__ float    g_dtwT[RRANK*DI];
__device__ float    g_bns[768];
__device__ float    g_bnb[768];
__device__ float    g_A  [DI*NST];

// ---------------- activations ----------------
__device__ __forceinline__ float siluf(float x){ return x / (1.0f + __expf(-x)); }
__device__ __forceinline__ float geluf(float x){ return 0.5f*x*(1.0f + erff(x*0.70710678118654752f)); }
__device__ __forceinline__ float softplusf(float x){ return fmaxf(x,0.0f) + log1pf(__expf(-fabsf(x))); }
template<int ACT>
__device__ __forceinline__ float act_apply(float v){
  if (ACT==1) return geluf(v);
  if (ACT==2) return siluf(v);
  return v;
}

// ---------------- mma helpers ----------------
__device__ __forceinline__ void ldsm4(unsigned &r0, unsigned &r1, unsigned &r2, unsigned &r3, unsigned addr){
  asm volatile("ldmatrix.sync.aligned.m8n8.x4.shared.b16 {%0,%1,%2,%3}, [%4];"
    : "=r"(r0),"=r"(r1),"=r"(r2),"=r"(r3) : "r"(addr));
}
__device__ __forceinline__ void mma16816(float d[4], const unsigned a[4], unsigned b0, unsigned b1){
  asm volatile("mma.sync.aligned.m16n8k16.row.col.f32.bf16.bf16.f32 "
    "{%0,%1,%2,%3}, {%4,%5,%6,%7}, {%8,%9}, {%0,%1,%2,%3};"
    : "+f"(d[0]),"+f"(d[1]),"+f"(d[2]),"+f"(d[3])
    : "r"(a[0]),"r"(a[1]),"r"(a[2]),"r"(a[3]), "r"(b0),"r"(b1));
}

// ---------------- prep ----------------
__global__ void prep_kernel(const float* __restrict__ g1,const float* __restrict__ b1,
                            const float* __restrict__ m1,const float* __restrict__ v1,
                            const float* __restrict__ g2,const float* __restrict__ b2,
                            const float* __restrict__ m2,const float* __restrict__ v2,
                            const float* __restrict__ g3,const float* __restrict__ b3,
                            const float* __restrict__ m3,const float* __restrict__ v3,
                            const float* __restrict__ g4,const float* __restrict__ b4,
                            const float* __restrict__ m4,const float* __restrict__ v4,
                            const float* __restrict__ A_log, const float* __restrict__ dt_w)
{
  int i = blockIdx.x*256 + threadIdx.x;
  const float eps = 1e-5f;
  if (i < 96){  float s = g1[i]*rsqrtf(v1[i]+eps); g_bns[i]     = s; g_bnb[i]     = b1[i]-m1[i]*s; }
  if (i < 192){ float s = g2[i]*rsqrtf(v2[i]+eps); g_bns[192+i] = s; g_bnb[192+i] = b2[i]-m2[i]*s;
                      s = g3[i]*rsqrtf(v3[i]+eps); g_bns[384+i] = s; g_bnb[384+i] = b3[i]-m3[i]*s;
                      s = g4[i]*rsqrtf(v4[i]+eps); g_bns[576+i] = s; g_bnb[576+i] = b4[i]-m4[i]*s; }
  if (i < DI*NST) g_A[i] = -expf(A_log[i]);
  if (i < DI*RRANK){ int d = i/RRANK, r = i - d*RRANK; g_dtwT[r*DI + d] = dt_w[i]; }
}

// ---------------- pack 5 weight arrays in one launch ----------------
#define PK_W2   (D_MID*D_IN)
#define PK_INW  (768*D_MID)
#define PK_XPW  (DBL_W*DI)
#define PK_OUTW (D_MID*DI)
#define PK_W3   (D_MID*D_MID)
__global__ void pack_all(const float* __restrict__ w2, const float* __restrict__ in_w,
                         const float* __restrict__ xp_w, const float* __restrict__ out_w,
                         const float* __restrict__ w3)
{
  int i = blockIdx.x*256 + threadIdx.x;
  int o = i;
  if (o < PK_W2){ g_w2p[o] = packf(w2[o]); return; }  o -= PK_W2;
  if (o < PK_INW){ g_inwp[o] = packf(in_w[o]); return; } o -= PK_INW;
  if (o < PK_XPW){ g_xpwp[o] = packf(xp_w[o]); return; } o -= PK_XPW;
  if (o < PK_OUTW){ g_outwp[o] = packf(out_w[o]); return; } o -= PK_OUTW;
  if (o < PK_W3){ g_w3p[o] = packf(w3[o]); }
}
#define PK_TOTAL (PK_W2+PK_INW+PK_XPW+PK_OUTW+PK_W3)

// ---------------- transpose NCHW -> token-major (packed) ----------------
__global__ void transpose_in(const float* __restrict__ x, unsigned* __restrict__ out)
{
  __shared__ float tile[32][33];
  int bc = blockIdx.x, bl = blockIdx.y, b = blockIdx.z;
  int tx = threadIdx.x, ty = threadIdx.y;
  #pragma unroll
  for (int i = ty; i < 32; i += 8)
    tile[i][tx] = x[(b*D_IN + bc*32 + i)*LSEQ + bl*32 + tx];
  __syncthreads();
  #pragma unroll
  for (int i = ty; i < 32; i += 8)
    out[(b*LSEQ + bl*32 + i)*D_IN + bc*32 + tx] = packf(tile[tx][i]);
}

// ---------------- weight transform: (O,C,3,3) -> packed (tap,O,Cin) ----------------
__global__ void transform_w(const float* __restrict__ w, unsigned* __restrict__ wt, int O, int Cin)
{
  int idx = blockIdx.x*256 + threadIdx.x;
  int total = O*Cin*9;
  if (idx < total){
    int o = idx/(Cin*9); int r = idx - o*(Cin*9); int c = r/9; int t = r - c*9;
    wt[((size_t)(t*O + o))*Cin + c] = packf(w[idx]);
  }
}

// ---------------- tile config ----------------
#define BM 64
#define BN 64
#define BKC 32
#define BKP 40

// =====================================================================
// Packed-pair NT GEMM, ping-pong pipelined (1 barrier / chunk).
// =====================================================================
template<int ACT, bool OUTP>
__global__ void __launch_bounds__(128)
gemm_nt(const unsigned* __restrict__ A, int lda,
        const unsigned* __restrict__ B,
        void* __restrict__ Cv,
        int N, int K,
        const float* __restrict__ scale, const float* __restrict__ shift)
{
  __shared__ __align__(16) unsigned short Ah[2][BM][BKP], Al[2][BM][BKP], Bh[2][BN][BKP], Bl[2][BN][BKP];
  const int tid  = threadIdx.x;
  const int lane = tid & 31;
  const int warp = tid >> 5;
  const int row0 = blockIdx.x * BM;
  const int col0 = blockIdx.y * BN;
  const int wm = (warp >> 1) * 32;
  const int wn = (warp &  1) * 32;

  float d[2][4][4];
  #pragma unroll
  for (int i=0;i<2;i++)
    #pragma unroll
    for (int j=0;j<4;j++)
      { d[i][j][0]=0.f; d[i][j][1]=0.f; d[i][j][2]=0.f; d[i][j][3]=0.f; }

  const int ai = tid >> 1;
  const int ak = (tid & 1) * 16;
  const bool jv = (col0 + ai) < N;
  const int lrow = lane & 15, lcol = (lane >> 4) * 8;

  const int nch = K / BKC;
  uint4 pa0,pa1,pa2,pa3, pb0,pb1,pb2,pb3;

  auto gload = [&](int c){
    const uint4* Ap = (const uint4*)(A + (size_t)(row0 + ai)*lda + c*BKC + ak);
    pa0=Ap[0]; pa1=Ap[1]; pa2=Ap[2]; pa3=Ap[3];
    if (jv){
      const uint4* Bp = (const uint4*)(B + (size_t)(col0 + ai)*K + c*BKC + ak);
      pb0=Bp[0]; pb1=Bp[1]; pb2=Bp[2]; pb3=Bp[3];
    } else {
      pb0=make_uint4(0,0,0,0); pb1=pb0; pb2=pb0; pb3=pb0;
    }
  };
  auto sstore = [&](int buf){
    uint4 h,l;
    unzip8(pa0,pa1,h,l);
    *(uint4*)&Ah[buf][ai][ak]   = h;  *(uint4*)&Al[buf][ai][ak]   = l;
    unzip8(pa2,pa3,h,l);
    *(uint4*)&Ah[buf][ai][ak+8] = h;  *(uint4*)&Al[buf][ai][ak+8] = l;
    unzip8(pb0,pb1,h,l);
    *(uint4*)&Bh[buf][ai][ak]   = h;  *(uint4*)&Bl[buf][ai][ak]   = l;
    unzip8(pb2,pb3,h,l);
    *(uint4*)&Bh[buf][ai][ak+8] = h;  *(uint4*)&Bl[buf][ai][ak+8] = l;
  };

  gload(0); sstore(0);
  __syncthreads();

  int cur = 0;
  for (int c = 0; c < nch; ++c){
    const bool more = (c+1 < nch);
    if (more) gload(c+1);

    const unsigned aH = (unsigned)__cvta_generic_to_shared(&Ah[cur][0][0]);
    const unsigned aL = (unsigned)__cvta_generic_to_shared(&Al[cur][0][0]);
    const unsigned bH = (unsigned)__cvta_generic_to_shared(&Bh[cur][0][0]);
    const unsigned bL = (unsigned)__cvta_generic_to_shared(&Bl[cur][0][0]);
    #pragma unroll
    for (int ks = 0; ks < BKC; ks += 16){
      unsigned ah[2][4], al[2][4], bh[2][4], bl[2][4];
      const unsigned oA0 = (unsigned)(((wm +      lrow)*BKP + ks + lcol)*2);
      const unsigned oA1 = (unsigned)(((wm + 16 + lrow)*BKP + ks + lcol)*2);
      const unsigned oB0 = (unsigned)(((wn +      lrow)*BKP + ks + lcol)*2);
      const unsigned oB1 = (unsigned)(((wn + 16 + lrow)*BKP + ks + lcol)*2);
      ldsm4(ah[0][0],ah[0][1],ah[0][2],ah[0][3], aH + oA0);
      ldsm4(ah[1][0],ah[1][1],ah[1][2],ah[1][3], aH + oA1);
      ldsm4(al[0][0],al[0][1],al[0][2],al[0][3], aL + oA0);
      ldsm4(al[1][0],al[1][1],al[1][2],al[1][3], aL + oA1);
      ldsm4(bh[0][0],bh[0][1],bh[0][2],bh[0][3], bH + oB0);
      ldsm4(bh[1][0],bh[1][1],bh[1][2],bh[1][3], bH + oB1);
      ldsm4(bl[0][0],bl[0][1],bl[0][2],bl[0][3], bL + oB0);
      ldsm4(bl[1][0],bl[1][1],bl[1][2],bl[1][3], bL + oB1);
      #pragma unroll
      for (int mf=0; mf<2; ++mf){
        #pragma unroll
        for (int nf=0; nf<4; ++nf){
          const int g = nf >> 1, s = nf & 1;
          mma16816(d[mf][nf], ah[mf], bh[g][s], bh[g][2+s]);
          mma16816(d[mf][nf], al[mf], bh[g][s], bh[g][2+s]);
          mma16816(d[mf][nf], ah[mf], bl[g][s], bl[g][2+s]);
        }
      }
    }
    if (more) sstore(cur^1);
    __syncthreads();
    cur ^= 1;
  }

  const int lr = lane >> 2;
  const int lc = (lane & 3) * 2;
  #pragma unroll
  for (int mf=0; mf<2; ++mf){
    #pragma unroll
    for (int nf=0; nf<4; ++nf){
      int gm = row0 + wm + mf*16 + lr;
      int gn = col0 + wn + nf*8 + lc;
      #pragma unroll
      for (int r=0; r<4; ++r){
        int m = gm + (r>>1)*8;
        int n = gn + (r&1);
        if (n < N){
          float sc = scale ? scale[n] : 1.f;
          float sb = shift ? shift[n] : 0.f;
          float o = act_apply<ACT>(d[mf][nf][r]*sc + sb);
          if (OUTP) ((unsigned*)Cv)[(size_t)m*N + n] = packf(o);
          else      ((float*)Cv)  [(size_t)m*N + n] = o;
        }
      }
    }
  }
}

// =====================================================================
// 3x3 conv implicit GEMM, packed pairs, flattened tap x chunk pipeline.
// =====================================================================
template<int ACT, bool NCHW_OUT>
__global__ void __launch_bounds__(128)
conv3x3_gemm(const unsigned* __restrict__ X,
             const unsigned* __restrict__ Wt,
             void* __restrict__ Cv,
             int Cin, int N,
             const float* __restrict__ scale, const float* __restrict__ shift)
{
  __shared__ __align__(16) unsigned short Ah[2][BM][BKP], Al[2][BM][BKP], Bh[2][BN][BKP], Bl[2][BN][BKP];
  const int tid  = threadIdx.x;
  const int lane = tid & 31;
  const int warp = tid >> 5;
  const int row0 = blockIdx.x * BM;
  const int col0 = blockIdx.y * BN;
  const int wm = (warp >> 1) * 32;
  const int wn = (warp &  1) * 32;

  float d[2][4][4];
  #pragma unroll
  for (int i=0;i<2;i++)
    #pragma unroll
    for (int j=0;j<4;j++)
      { d[i][j][0]=0.f; d[i][j][1]=0.f; d[i][j][2]=0.f; d[i][j][3]=0.f; }

  const int ai = tid >> 1;
  const int ak = (tid & 1) * 16;
  const bool jv = (col0 + ai) < N;

  const int gt = row0 + ai;
  const int bb = gt >> 10;
  const int ll = gt & 1023;
  const int hh = ll >> 5, ww = ll & 31;
  const int lrow = lane & 15, lcol = (lane >> 4) * 8;

  const int kpt = Cin / BKC;
  const int nch = 9 * kpt;
  uint4 pa0,pa1,pa2,pa3, pb0,pb1,pb2,pb3;

  auto gload = [&](int c){
    int tap = c / kpt;
    int c0  = (c - tap*kpt) * BKC;
    int t3  = tap / 3;
    int dy  = t3 - 1, dx = tap - t3*3 - 1;
    int nh  = hh + dy, nw = ww + dx;
    bool valid = ((unsigned)nh < 32u) && ((unsigned)nw < 32u);
    if (valid){
      const uint4* Ap = (const uint4*)(X + (size_t)((bb<<10) + (nh<<5) + nw)*Cin + c0 + ak);
      pa0=Ap[0]; pa1=Ap[1]; pa2=Ap[2]; pa3=Ap[3];
    } else {
      pa0=make_uint4(0,0,0,0); pa1=pa0; pa2=pa0; pa3=pa0;
    }
    if (jv){
      const uint4* Bp = (const uint4*)(Wt + ((size_t)(tap*N + col0 + ai))*Cin + c0 + ak);
      pb0=Bp[0]; pb1=Bp[1]; pb2=Bp[2]; pb3=Bp[3];
    } else {
      pb0=make_uint4(0,0,0,0); pb1=pb0; pb2=pb0; pb3=pb0;
    }
  };
  auto sstore = [&](int buf){
    uint4 h,l;
    unzip8(pa0,pa1,h,l);
    *(uint4*)&Ah[buf][ai][ak]   = h;  *(uint4*)&Al[buf][ai][ak]   = l;
    unzip8(pa2,pa3,h,l);
    *(uint4*)&Ah[buf][ai][ak+8] = h;  *(uint4*)&Al[buf][ai][ak+8] = l;
    unzip8(pb0,pb1,h,l);
    *(uint4*)&Bh[buf][ai][ak]   = h;  *(uint4*)&Bl[buf][ai][ak]   = l;
    unzip8(pb2,pb3,h,l);
    *(uint4*)&Bh[buf][ai][ak+8] = h;  *(uint4*)&Bl[buf][ai][ak+8] = l;
  };

  gload(0); sstore(0);
  __syncthreads();

  int cur = 0;
  for (int c = 0; c < nch; ++c){
    const bool more = (c+1 < nch);
    if (more) gload(c+1);

    const unsigned aH = (unsigned)__cvta_generic_to_shared(&Ah[cur][0][0]);
    const unsigned aL = (unsigned)__cvta_generic_to_shared(&Al[cur][0][0]);
    const unsigned bH = (unsigned)__cvta_generic_to_shared(&Bh[cur][0][0]);
    const unsigned bL = (unsigned)__cvta_generic_to_shared(&Bl[cur][0][0]);
    #pragma unroll
    for (int ks = 0; ks < BKC; ks += 16){
      unsigned ah[2][4], al[2][4], bh[2][4], bl[2][4];
      const unsigned oA0 = (unsigned)(((wm +      lrow)*BKP + ks + lcol)*2);
      const unsigned oA1 = (unsigned)(((wm + 16 + lrow)*BKP + ks + lcol)*2);
      const unsigned oB0 = (unsigned)(((wn +      lrow)*BKP + ks + lcol)*2);
      const unsigned oB1 = (unsigned)(((wn + 16 + lrow)*BKP + ks + lcol)*2);
      ldsm4(ah[0][0],ah[0][1],ah[0][2],ah[0][3], aH + oA0);
      ldsm4(ah[1][0],ah[1][1],ah[1][2],ah[1][3], aH + oA1);
      ldsm4(al[0][0],al[0][1],al[0][2],al[0][3], aL + oA0);
      ldsm4(al[1][0],al[1][1],al[1][2],al[1][3], aL + oA1);
      ldsm4(bh[0][0],bh[0][1],bh[0][2],bh[0][3], bH + oB0);
      ldsm4(bh[1][0],bh[1][1],bh[1][2],bh[1][3], bH + oB1);
      ldsm4(bl[0][0],bl[0][1],bl[0][2],bl[0][3], bL + oB0);
      ldsm4(bl[1][0],bl[1][1],bl[1][2],bl[1][3], bL + oB1);
      #pragma unroll
      for (int mf=0; mf<2; ++mf){
        #pragma unroll
        for (int nf=0; nf<4; ++nf){
          const int g = nf >> 1, s = nf & 1;
          mma16816(d[mf][nf], ah[mf], bh[g][s], bh[g][2+s]);
          mma16816(d[mf][nf], al[mf], bh[g][s], bh[g][2+s]);
          mma16816(d[mf][nf], ah[mf], bl[g][s], bl[g][2+s]);
        }
      }
    }
    if (more) sstore(cur^1);
    __syncthreads();
    cur ^= 1;
  }

  const int lr = lane >> 2;
  const int lc = (lane & 3) * 2;
  #pragma unroll
  for (int mf=0; mf<2; ++mf){
    #pragma unroll
    for (int nf=0; nf<4; ++nf){
      int gm = row0 + wm + mf*16 + lr;
      int gn = col0 + wn + nf*8 + lc;
      #pragma unroll
      for (int r=0; r<4; ++r){
        int m = gm + (r>>1)*8;
        int n = gn + (r&1);
        if (n < N){
          float sc = scale ? scale[n] : 1.f;
          float sb = shift ? shift[n] : 0.f;
          float o = act_apply<ACT>(d[mf][nf][r]*sc + sb);
          if (NCHW_OUT){
            int ob = m >> 10, ol = m & 1023;
            ((float*)Cv)[(size_t)(ob*N + n)*LSEQ + ol] = o;
          } else {
            ((unsigned*)Cv)[(size_t)m*N + n] = packf(o);
          }
        }
      }
    }
  }
}

// ---------------- causal depthwise conv (K=4) + SiLU ----------------
__global__ void dwconv_silu(const float* __restrict__ cw, const float* __restrict__ cb)
{
  int idx = blockIdx.x*256 + threadIdx.x;
  if (idx >= NTOK*DI) return;
  int d = idx % DI;
  int tok = idx / DI;
  int b = tok >> 10, l = tok & 1023;
  float acc = cb[d];
  const unsigned* xi = g_xz + (size_t)(b<<10)*768 + d;
  #pragma unroll
  for (int k=0;k<4;++k){
    int ll = l + k - 3;
    if (ll >= 0) acc = fmaf(unpackf(xi[(size_t)ll*768]), cw[d*4+k], acc);
  }
  g_xc[idx] = packf(siluf(acc));
}

// ---------------- dt-proj (K=12) + softplus, SIMT ----------------
__global__ void dtproj_kernel(const float* __restrict__ dt_b)
{
  int idx = blockIdx.x*256 + threadIdx.x;
  if (idx >= NTOK*DI) return;
  int d = idx % DI;
  int t = idx / DI;
  const float* row = g_dbl + (size_t)t*DBL_W;
  float acc = dt_b[d];
  #pragma unroll
  for (int r=0;r<RRANK;++r)
    acc = fmaf(__ldg(row + r), g_dtwT[r*DI + d], acc);
  g_dt[idx] = softplusf(acc);
}

// ---------------- selective scan ----------------
__global__ void __launch_bounds__(128)
scan_kernel(const float* __restrict__ Dp)
{
  int gid = (blockIdx.x * 128 + threadIdx.x) >> 4;
  int n   = threadIdx.x & 15;
  int b   = gid / DI;
  int d   = gid - b*DI;
  float Aval = g_A[d*NST + n];
  float dpv  = Dp[d];
  float h = 0.f;
  const float*    __restrict__ dtp = g_dt  + (size_t)(b<<10)*DI + d;
  const unsigned* __restrict__ xcp = g_xc  + (size_t)(b<<10)*DI + d;
  const unsigned* __restrict__ zp  = g_xz  + (size_t)(b<<10)*768 + 384 + d;
  const float*    __restrict__ blp = g_dbl + (size_t)(b<<10)*DBL_W;
  unsigned* __restrict__ yp = g_y + (size_t)(b<<10)*DI + d;

  #pragma unroll 4
  for (int l = 0; l < LSEQ; ++l){
    float dtv = dtp[(size_t)l*DI];
    float xcv = unpackf(xcp[(size_t)l*DI]);
    float Bv  = blp[(size_t)l*DBL_W + RRANK + n];
    float Cv  = blp[(size_t)l*DBL_W + RRANK + NST + n];
    float dA  = __expf(dtv * Aval);
    h = fmaf(dA, h, dtv*Bv*xcv);
    float p = h * Cv;
    p += __shfl_xor_sync(0xffffffffu, p, 8, 16);
    p += __shfl_xor_sync(0xffffffffu, p, 4, 16);
    p += __shfl_xor_sync(0xffffffffu, p, 2, 16);
    p += __shfl_xor_sync(0xffffffffu, p, 1, 16);
    if (n == 0){
      float zv = unpackf(zp[(size_t)l*768]);
      yp[(size_t)l*DI] = packf((p + xcv*dpv) * siluf(zv));
    }
  }
}

// ---------------- host launcher ----------------
extern "C" void kernel_launch(void* const* d_in, const int* in_sizes, int n_in,
                              void* d_out, int out_size)
{
  (void)in_sizes; (void)n_in; (void)out_size;
  const float* x    = (const float*)d_in[0];
  const float* w1   = (const float*)d_in[1];
  const float* g1   = (const float*)d_in[2];
  const float* b1   = (const float*)d_in[3];
  const float* m1   = (const float*)d_in[4];
  const float* v1   = (const float*)d_in[5];
  const float* w2   = (const float*)d_in[6];
  const float* g2   = (const float*)d_in[7];
  const float* b2   = (const float*)d_in[8];
  const float* m2   = (const float*)d_in[9];
  const float* v2   = (const float*)d_in[10];
  const float* in_w = (const float*)d_in[11];
  const float* cw   = (const float*)d_in[12];
  const float* cb   = (const float*)d_in[13];
  const float* xp_w = (const float*)d_in[14];
  const float* dt_w = (const float*)d_in[15];
  const float* dt_b = (const float*)d_in[16];
  const float* A_log= (const float*)d_in[17];
  const float* Dp   = (const float*)d_in[18];
  const float* out_w= (const float*)d_in[19];
  const float* w3   = (const float*)d_in[20];
  const float* g3   = (const float*)d_in[21];
  const float* b3   = (const float*)d_in[22];
  const float* m3   = (const float*)d_in[23];
  const float* v3   = (const float*)d_in[24];
  const float* w4   = (const float*)d_in[25];
  const float* g4   = (const float*)d_in[26];
  const float* b4   = (const float*)d_in[27];
  const float* m4   = (const float*)d_in[28];
  const float* v4   = (const float*)d_in[29];

  unsigned *p_xt,*p_t1,*p_t2,*p_xz,*p_xc,*p_y,*p_t3,*p_t4,*p_w1t,*p_w4t;
  unsigned *p_w2p,*p_inwp,*p_xpwp,*p_outwp,*p_w3p;
  float *p_dbl,*p_bns,*p_bnb;
  cudaGetSymbolAddress((void**)&p_xt , g_xt );
  cudaGetSymbolAddress((void**)&p_t1 , g_t1 );
  cudaGetSymbolAddress((void**)&p_t2 , g_t2 );
  cudaGetSymbolAddress((void**)&p_xz , g_xz );
  cudaGetSymbolAddress((void**)&p_xc , g_xc );
  cudaGetSymbolAddress((void**)&p_y  , g_y  );
  cudaGetSymbolAddress((void**)&p_t3 , g_t3 );
  cudaGetSymbolAddress((void**)&p_t4 , g_t4 );
  cudaGetSymbolAddress((void**)&p_w1t, g_w1t);
  cudaGetSymbolAddress((void**)&p_w4t, g_w4t);
  cudaGetSymbolAddress((void**)&p_w2p, g_w2p);
  cudaGetSymbolAddress((void**)&p_inwp, g_inwp);
  cudaGetSymbolAddress((void**)&p_xpwp, g_xpwp);
  cudaGetSymbolAddress((void**)&p_outwp, g_outwp);
  cudaGetSymbolAddress((void**)&p_w3p, g_w3p);
  cudaGetSymbolAddress((void**)&p_dbl, g_dbl);
  cudaGetSymbolAddress((void**)&p_bns, g_bns);
  cudaGetSymbolAddress((void**)&p_bnb, g_bnb);

  // conv1 at my 0-based launch #3 (ncu-captured slot)
  prep_kernel<<<24,256>>>(g1,b1,m1,v1, g2,b2,m2,v2, g3,b3,m3,v3, g4,b4,m4,v4, A_log, dt_w); // #0
  transpose_in<<<dim3(3,32,8), dim3(32,8)>>>(x, p_xt);                                       // #1
  transform_w<<<(D_IN*D_IN*9+255)/256,256>>>(w1, p_w1t, D_IN, D_IN);                         // #2
  conv3x3_gemm<1,false><<<dim3(NTOK/BM, 2),128>>>(p_xt, p_w1t, p_t1, D_IN, D_IN, p_bns+0, p_bnb+0); // #3
  transform_w<<<(D_MID*D_MID*9+255)/256,256>>>(w4, p_w4t, D_MID, D_MID);                     // #4
  pack_all<<<(PK_TOTAL+255)/256,256>>>(w2, in_w, xp_w, out_w, w3);

  gemm_nt<2,true><<<dim3(NTOK/BM, 3),128>>>(p_t1, D_IN, p_w2p, p_t2, D_MID, D_IN, p_bns+192, p_bnb+192);
  gemm_nt<0,true><<<dim3(NTOK/BM, 12),128>>>(p_t2, D_MID, p_inwp, p_xz, 768, D_MID, nullptr, nullptr);
  dwconv_silu<<<(NTOK*DI)/256,256>>>(cw, cb);
  gemm_nt<0,false><<<dim3(NTOK/BM, 1),128>>>(p_xc, DI, p_xpwp, p_dbl, DBL_W, DI, nullptr, nullptr);
  dtproj_kernel<<<(NTOK*DI)/256,256>>>(dt_b);
  scan_kernel<<<(NTOK/LSEQ)*DI*16/128,128>>>(Dp);
  gemm_nt<0,true><<<dim3(NTOK/BM, 3),128>>>(p_y, DI, p_outwp, p_t3, D_MID, DI, nullptr, nullptr);
  gemm_nt<2,true><<<dim3(NTOK/BM, 3),128>>>(p_t3, D_MID, p_w3p, p_t4, D_MID, D_MID, p_bns+384, p_bnb+384);
  conv3x3_gemm<1,true><<<dim3(NTOK/BM, 3),128>>>(p_t4, p_w4t, (float*)d_out, D_MID, D_MID, p_bns+576, p_bnb+576);
}

// round 10
// speedup vs baseline: 1.1955x; 1.0240x over previous
#include <cuda_runtime.h>
#include <cuda_bf16.h>
#include <math.h>

// ---------------- problem constants ----------------
#define NTOK   8192
#define LSEQ   1024
#define D_IN   96
#define D_MID  192
#define DI     384
#define NST    16
#define RRANK  12
#define DBL_W  44

// ---------------- packed bf16-pair format: u32 = hi | (lo<<16) ----------------
__device__ __forceinline__ unsigned packf(float x){
  __nv_bfloat16 h = __float2bfloat16_rn(x);
  float r = x - __bfloat162float(h);
  __nv_bfloat16 l = __float2bfloat16_rn(r);
  return (unsigned)__bfloat16_as_ushort(h) | ((unsigned)__bfloat16_as_ushort(l) << 16);
}
__device__ __forceinline__ float unpackf(unsigned p){
  __nv_bfloat16 h = __ushort_as_bfloat16((unsigned short)(p & 0xFFFF));
  __nv_bfloat16 l = __ushort_as_bfloat16((unsigned short)(p >> 16));
  return __bfloat162float(h) + __bfloat162float(l);
}
__device__ __forceinline__ void unzip8(uint4 p, uint4 q, uint4 &h, uint4 &l){
  h.x=__byte_perm(p.x,p.y,0x5410); h.y=__byte_perm(p.z,p.w,0x5410);
  h.z=__byte_perm(q.x,q.y,0x5410); h.w=__byte_perm(q.z,q.w,0x5410);
  l.x=__byte_perm(p.x,p.y,0x7632); l.y=__byte_perm(p.z,p.w,0x7632);
  l.z=__byte_perm(q.x,q.y,0x7632); l.w=__byte_perm(q.z,q.w,0x7632);
}

// ---------------- scratch ----------------
__device__ unsigned g_xt [NTOK*D_IN];
__device__ unsigned g_t1 [NTOK*D_IN];
__device__ unsigned g_t2 [NTOK*D_MID];
__device__ unsigned g_xz [NTOK*768];
__device__ unsigned g_xc [NTOK*DI];
__device__ unsigned g_y  [NTOK*DI];
__device__ unsigned g_t3 [NTOK*D_MID];
__device__ unsigned g_t4 [NTOK*D_MID];
__device__ float    g_dbl[NTOK*DBL_W];
__device__ float    g_dt [NTOK*DI];
__device__ unsigned g_w1t[9*D_IN*D_IN];
__device__ unsigned g_w4t[9*D_MID*D_MID];
__device__ unsigned g_w2p[D_MID*D_IN];
__device__ unsigned g_inwp[768*D_MID];
__device__ unsigned g_xpwp[DBL_W*DI];
__device__ unsigned g_outwp[D_MID*DI];
__device__ unsigned g_w3p[D_MID*D_MID];
__device__ float    g_dtwT[RRANK*DI];
__device__ float    g_bns[768];
__device__ float    g_bnb[768];
__device__ float    g_A  [DI*NST];

// ---------------- activations ----------------
__device__ __forceinline__ float siluf(float x){ return x / (1.0f + __expf(-x)); }
__device__ __forceinline__ float geluf(float x){ return 0.5f*x*(1.0f + erff(x*0.70710678118654752f)); }
__device__ __forceinline__ float softplusf(float x){ return fmaxf(x,0.0f) + log1pf(__expf(-fabsf(x))); }
template<int ACT>
__device__ __forceinline__ float act_apply(float v){
  if (ACT==1) return geluf(v);
  if (ACT==2) return siluf(v);
  return v;
}

// ---------------- mma helpers ----------------
__device__ __forceinline__ void ldsm4(unsigned &r0, unsigned &r1, unsigned &r2, unsigned &r3, unsigned addr){
  asm volatile("ldmatrix.sync.aligned.m8n8.x4.shared.b16 {%0,%1,%2,%3}, [%4];"
    : "=r"(r0),"=r"(r1),"=r"(r2),"=r"(r3) : "r"(addr));
}
__device__ __forceinline__ void mma16816(float d[4], const unsigned a[4], unsigned b0, unsigned b1){
  asm volatile("mma.sync.aligned.m16n8k16.row.col.f32.bf16.bf16.f32 "
    "{%0,%1,%2,%3}, {%4,%5,%6,%7}, {%8,%9}, {%0,%1,%2,%3};"
    : "+f"(d[0]),"+f"(d[1]),"+f"(d[2]),"+f"(d[3])
    : "r"(a[0]),"r"(a[1]),"r"(a[2]),"r"(a[3]), "r"(b0),"r"(b1));
}

// ---------------- prep ----------------
__global__ void prep_kernel(const float* __restrict__ g1,const float* __restrict__ b1,
                            const float* __restrict__ m1,const float* __restrict__ v1,
                            const float* __restrict__ g2,const float* __restrict__ b2,
                            const float* __restrict__ m2,const float* __restrict__ v2,
                            const float* __restrict__ g3,const float* __restrict__ b3,
                            const float* __restrict__ m3,const float* __restrict__ v3,
                            const float* __restrict__ g4,const float* __restrict__ b4,
                            const float* __restrict__ m4,const float* __restrict__ v4,
                            const float* __restrict__ A_log, const float* __restrict__ dt_w)
{
  int i = blockIdx.x*256 + threadIdx.x;
  const float eps = 1e-5f;
  if (i < 96){  float s = g1[i]*rsqrtf(v1[i]+eps); g_bns[i]     = s; g_bnb[i]     = b1[i]-m1[i]*s; }
  if (i < 192){ float s = g2[i]*rsqrtf(v2[i]+eps); g_bns[192+i] = s; g_bnb[192+i] = b2[i]-m2[i]*s;
                      s = g3[i]*rsqrtf(v3[i]+eps); g_bns[384+i] = s; g_bnb[384+i] = b3[i]-m3[i]*s;
                      s = g4[i]*rsqrtf(v4[i]+eps); g_bns[576+i] = s; g_bnb[576+i] = b4[i]-m4[i]*s; }
  if (i < DI*NST) g_A[i] = -expf(A_log[i]);
  if (i < DI*RRANK){ int d = i/RRANK, r = i - d*RRANK; g_dtwT[r*DI + d] = dt_w[i]; }
}

// ---------------- all weight transforms/packs in ONE launch ----------------
#define TW1   (D_IN*D_IN*9)
#define TW4   (D_MID*D_MID*9)
#define PK_W2   (D_MID*D_IN)
#define PK_INW  (768*D_MID)
#define PK_XPW  (DBL_W*DI)
#define PK_OUTW (D_MID*DI)
#define PK_W3   (D_MID*D_MID)
#define PW_TOTAL (TW1+TW4+PK_W2+PK_INW+PK_XPW+PK_OUTW+PK_W3)
__global__ void prep_weights(const float* __restrict__ w1, const float* __restrict__ w4,
                             const float* __restrict__ w2, const float* __restrict__ in_w,
                             const float* __restrict__ xp_w, const float* __restrict__ out_w,
                             const float* __restrict__ w3)
{
  int i = blockIdx.x*256 + threadIdx.x;
  int o = i;
  if (o < TW1){
    int oo = o/(D_IN*9); int r = o - oo*(D_IN*9); int c = r/9; int t = r - c*9;
    g_w1t[((size_t)(t*D_IN + oo))*D_IN + c] = packf(w1[o]); return;
  } o -= TW1;
  if (o < TW4){
    int oo = o/(D_MID*9); int r = o - oo*(D_MID*9); int c = r/9; int t = r - c*9;
    g_w4t[((size_t)(t*D_MID + oo))*D_MID + c] = packf(w4[o]); return;
  } o -= TW4;
  if (o < PK_W2){ g_w2p[o] = packf(w2[o]); return; }  o -= PK_W2;
  if (o < PK_INW){ g_inwp[o] = packf(in_w[o]); return; } o -= PK_INW;
  if (o < PK_XPW){ g_xpwp[o] = packf(xp_w[o]); return; } o -= PK_XPW;
  if (o < PK_OUTW){ g_outwp[o] = packf(out_w[o]); return; } o -= PK_OUTW;
  if (o < PK_W3){ g_w3p[o] = packf(w3[o]); }
}

// ---------------- transpose NCHW -> token-major (packed) ----------------
__global__ void transpose_in(const float* __restrict__ x, unsigned* __restrict__ out)
{
  __shared__ float tile[32][33];
  int bc = blockIdx.x, bl = blockIdx.y, b = blockIdx.z;
  int tx = threadIdx.x, ty = threadIdx.y;
  #pragma unroll
  for (int i = ty; i < 32; i += 8)
    tile[i][tx] = x[(b*D_IN + bc*32 + i)*LSEQ + bl*32 + tx];
  __syncthreads();
  #pragma unroll
  for (int i = ty; i < 32; i += 8)
    out[(b*LSEQ + bl*32 + i)*D_IN + bc*32 + tx] = packf(tile[tx][i]);
}

// ---------------- tile config ----------------
#define BM 64
#define BN 64
#define BKC 32
#define BKP 40

// =====================================================================
// Packed-pair NT GEMM: 256 threads (8 warps, 2m x 4n, each m32n16),
// ping-pong pipeline, 1 barrier/chunk.
// =====================================================================
template<int ACT, bool OUTP>
__global__ void __launch_bounds__(256)
gemm_nt(const unsigned* __restrict__ A, int lda,
        const unsigned* __restrict__ B,
        void* __restrict__ Cv,
        int N, int K,
        const float* __restrict__ scale, const float* __restrict__ shift)
{
  __shared__ __align__(16) unsigned short Ah[2][BM][BKP], Al[2][BM][BKP], Bh[2][BN][BKP], Bl[2][BN][BKP];
  const int tid  = threadIdx.x;
  const int lane = tid & 31;
  const int warp = tid >> 5;
  const int row0 = blockIdx.x * BM;
  const int col0 = blockIdx.y * BN;
  const int wm = (warp >> 2) * 32;   // 0 or 32
  const int wn = (warp &  3) * 16;   // 0,16,32,48

  float d[2][2][4];
  #pragma unroll
  for (int i=0;i<2;i++)
    #pragma unroll
    for (int j=0;j<2;j++)
      { d[i][j][0]=0.f; d[i][j][1]=0.f; d[i][j][2]=0.f; d[i][j][3]=0.f; }

  const int ai = tid >> 2;          // 0..63
  const int ak = (tid & 3) * 8;     // 0,8,16,24
  const bool jv = (col0 + ai) < N;
  const int lrow = lane & 15, lcol = (lane >> 4) * 8;

  const int nch = K / BKC;
  uint4 pa0,pa1, pb0,pb1;

  auto gload = [&](int c){
    const uint4* Ap = (const uint4*)(A + (size_t)(row0 + ai)*lda + c*BKC + ak);
    pa0=Ap[0]; pa1=Ap[1];
    if (jv){
      const uint4* Bp = (const uint4*)(B + (size_t)(col0 + ai)*K + c*BKC + ak);
      pb0=Bp[0]; pb1=Bp[1];
    } else {
      pb0=make_uint4(0,0,0,0); pb1=pb0;
    }
  };
  auto sstore = [&](int buf){
    uint4 h,l;
    unzip8(pa0,pa1,h,l);
    *(uint4*)&Ah[buf][ai][ak] = h;  *(uint4*)&Al[buf][ai][ak] = l;
    unzip8(pb0,pb1,h,l);
    *(uint4*)&Bh[buf][ai][ak] = h;  *(uint4*)&Bl[buf][ai][ak] = l;
  };

  gload(0); sstore(0);
  __syncthreads();

  int cur = 0;
  for (int c = 0; c < nch; ++c){
    const bool more = (c+1 < nch);
    if (more) gload(c+1);

    const unsigned aH = (unsigned)__cvta_generic_to_shared(&Ah[cur][0][0]);
    const unsigned aL = (unsigned)__cvta_generic_to_shared(&Al[cur][0][0]);
    const unsigned bH = (unsigned)__cvta_generic_to_shared(&Bh[cur][0][0]);
    const unsigned bL = (unsigned)__cvta_generic_to_shared(&Bl[cur][0][0]);
    #pragma unroll
    for (int ks = 0; ks < BKC; ks += 16){
      unsigned ah[2][4], al[2][4], bh[4], bl[4];
      const unsigned oA0 = (unsigned)(((wm +      lrow)*BKP + ks + lcol)*2);
      const unsigned oA1 = (unsigned)(((wm + 16 + lrow)*BKP + ks + lcol)*2);
      const unsigned oB  = (unsigned)(((wn +      lrow)*BKP + ks + lcol)*2);
      ldsm4(ah[0][0],ah[0][1],ah[0][2],ah[0][3], aH + oA0);
      ldsm4(ah[1][0],ah[1][1],ah[1][2],ah[1][3], aH + oA1);
      ldsm4(al[0][0],al[0][1],al[0][2],al[0][3], aL + oA0);
      ldsm4(al[1][0],al[1][1],al[1][2],al[1][3], aL + oA1);
      ldsm4(bh[0],bh[1],bh[2],bh[3], bH + oB);
      ldsm4(bl[0],bl[1],bl[2],bl[3], bL + oB);
      #pragma unroll
      for (int mf=0; mf<2; ++mf){
        #pragma unroll
        for (int nf=0; nf<2; ++nf){
          mma16816(d[mf][nf], ah[mf], bh[nf], bh[2+nf]);
          mma16816(d[mf][nf], al[mf], bh[nf], bh[2+nf]);
          mma16816(d[mf][nf], ah[mf], bl[nf], bl[2+nf]);
        }
      }
    }
    if (more) sstore(cur^1);
    __syncthreads();
    cur ^= 1;
  }

  const int lr = lane >> 2;
  const int lc = (lane & 3) * 2;
  #pragma unroll
  for (int mf=0; mf<2; ++mf){
    #pragma unroll
    for (int nf=0; nf<2; ++nf){
      int gm = row0 + wm + mf*16 + lr;
      int gn = col0 + wn + nf*8 + lc;
      #pragma unroll
      for (int r=0; r<4; ++r){
        int m = gm + (r>>1)*8;
        int n = gn + (r&1);
        if (n < N){
          float sc = scale ? scale[n] : 1.f;
          float sb = shift ? shift[n] : 0.f;
          float o = act_apply<ACT>(d[mf][nf][r]*sc + sb);
          if (OUTP) ((unsigned*)Cv)[(size_t)m*N + n] = packf(o);
          else      ((float*)Cv)  [(size_t)m*N + n] = o;
        }
      }
    }
  }
}

// =====================================================================
// 3x3 conv implicit GEMM, packed pairs, 256 threads, same pipeline.
// =====================================================================
template<int ACT, bool NCHW_OUT>
__global__ void __launch_bounds__(256)
conv3x3_gemm(const unsigned* __restrict__ X,
             const unsigned* __restrict__ Wt,
             void* __restrict__ Cv,
             int Cin, int N,
             const float* __restrict__ scale, const float* __restrict__ shift)
{
  __shared__ __align__(16) unsigned short Ah[2][BM][BKP], Al[2][BM][BKP], Bh[2][BN][BKP], Bl[2][BN][BKP];
  const int tid  = threadIdx.x;
  const int lane = tid & 31;
  const int warp = tid >> 5;
  const int row0 = blockIdx.x * BM;
  const int col0 = blockIdx.y * BN;
  const int wm = (warp >> 2) * 32;
  const int wn = (warp &  3) * 16;

  float d[2][2][4];
  #pragma unroll
  for (int i=0;i<2;i++)
    #pragma unroll
    for (int j=0;j<2;j++)
      { d[i][j][0]=0.f; d[i][j][1]=0.f; d[i][j][2]=0.f; d[i][j][3]=0.f; }

  const int ai = tid >> 2;
  const int ak = (tid & 3) * 8;
  const bool jv = (col0 + ai) < N;

  const int gt = row0 + ai;
  const int bb = gt >> 10;
  const int ll = gt & 1023;
  const int hh = ll >> 5, ww = ll & 31;
  const int lrow = lane & 15, lcol = (lane >> 4) * 8;

  const int kpt = Cin / BKC;
  const int nch = 9 * kpt;
  uint4 pa0,pa1, pb0,pb1;

  auto gload = [&](int c){
    int tap = c / kpt;
    int c0  = (c - tap*kpt) * BKC;
    int t3  = tap / 3;
    int dy  = t3 - 1, dx = tap - t3*3 - 1;
    int nh  = hh + dy, nw = ww + dx;
    bool valid = ((unsigned)nh < 32u) && ((unsigned)nw < 32u);
    if (valid){
      const uint4* Ap = (const uint4*)(X + (size_t)((bb<<10) + (nh<<5) + nw)*Cin + c0 + ak);
      pa0=Ap[0]; pa1=Ap[1];
    } else {
      pa0=make_uint4(0,0,0,0); pa1=pa0;
    }
    if (jv){
      const uint4* Bp = (const uint4*)(Wt + ((size_t)(tap*N + col0 + ai))*Cin + c0 + ak);
      pb0=Bp[0]; pb1=Bp[1];
    } else {
      pb0=make_uint4(0,0,0,0); pb1=pb0;
    }
  };
  auto sstore = [&](int buf){
    uint4 h,l;
    unzip8(pa0,pa1,h,l);
    *(uint4*)&Ah[buf][ai][ak] = h;  *(uint4*)&Al[buf][ai][ak] = l;
    unzip8(pb0,pb1,h,l);
    *(uint4*)&Bh[buf][ai][ak] = h;  *(uint4*)&Bl[buf][ai][ak] = l;
  };

  gload(0); sstore(0);
  __syncthreads();

  int cur = 0;
  for (int c = 0; c < nch; ++c){
    const bool more = (c+1 < nch);
    if (more) gload(c+1);

    const unsigned aH = (unsigned)__cvta_generic_to_shared(&Ah[cur][0][0]);
    const unsigned aL = (unsigned)__cvta_generic_to_shared(&Al[cur][0][0]);
    const unsigned bH = (unsigned)__cvta_generic_to_shared(&Bh[cur][0][0]);
    const unsigned bL = (unsigned)__cvta_generic_to_shared(&Bl[cur][0][0]);
    #pragma unroll
    for (int ks = 0; ks < BKC; ks += 16){
      unsigned ah[2][4], al[2][4], bh[4], bl[4];
      const unsigned oA0 = (unsigned)(((wm +      lrow)*BKP + ks + lcol)*2);
      const unsigned oA1 = (unsigned)(((wm + 16 + lrow)*BKP + ks + lcol)*2);
      const unsigned oB  = (unsigned)(((wn +      lrow)*BKP + ks + lcol)*2);
      ldsm4(ah[0][0],ah[0][1],ah[0][2],ah[0][3], aH + oA0);
      ldsm4(ah[1][0],ah[1][1],ah[1][2],ah[1][3], aH + oA1);
      ldsm4(al[0][0],al[0][1],al[0][2],al[0][3], aL + oA0);
      ldsm4(al[1][0],al[1][1],al[1][2],al[1][3], aL + oA1);
      ldsm4(bh[0],bh[1],bh[2],bh[3], bH + oB);
      ldsm4(bl[0],bl[1],bl[2],bl[3], bL + oB);
      #pragma unroll
      for (int mf=0; mf<2; ++mf){
        #pragma unroll
        for (int nf=0; nf<2; ++nf){
          mma16816(d[mf][nf], ah[mf], bh[nf], bh[2+nf]);
          mma16816(d[mf][nf], al[mf], bh[nf], bh[2+nf]);
          mma16816(d[mf][nf], ah[mf], bl[nf], bl[2+nf]);
        }
      }
    }
    if (more) sstore(cur^1);
    __syncthreads();
    cur ^= 1;
  }

  const int lr = lane >> 2;
  const int lc = (lane & 3) * 2;
  #pragma unroll
  for (int mf=0; mf<2; ++mf){
    #pragma unroll
    for (int nf=0; nf<2; ++nf){
      int gm = row0 + wm + mf*16 + lr;
      int gn = col0 + wn + nf*8 + lc;
      #pragma unroll
      for (int r=0; r<4; ++r){
        int m = gm + (r>>1)*8;
        int n = gn + (r&1);
        if (n < N){
          float sc = scale ? scale[n] : 1.f;
          float sb = shift ? shift[n] : 0.f;
          float o = act_apply<ACT>(d[mf][nf][r]*sc + sb);
          if (NCHW_OUT){
            int ob = m >> 10, ol = m & 1023;
            ((float*)Cv)[(size_t)(ob*N + n)*LSEQ + ol] = o;
          } else {
            ((unsigned*)Cv)[(size_t)m*N + n] = packf(o);
          }
        }
      }
    }
  }
}

// ---------------- causal depthwise conv (K=4) + SiLU ----------------
__global__ void dwconv_silu(const float* __restrict__ cw, const float* __restrict__ cb)
{
  int idx = blockIdx.x*256 + threadIdx.x;
  if (idx >= NTOK*DI) return;
  int d = idx % DI;
  int tok = idx / DI;
  int b = tok >> 10, l = tok & 1023;
  float acc = cb[d];
  const unsigned* xi = g_xz + (size_t)(b<<10)*768 + d;
  #pragma unroll
  for (int k=0;k<4;++k){
    int ll = l + k - 3;
    if (ll >= 0) acc = fmaf(unpackf(xi[(size_t)ll*768]), cw[d*4+k], acc);
  }
  g_xc[idx] = packf(siluf(acc));
}

// ---------------- dt-proj (K=12) + softplus ----------------
__global__ void dtproj_kernel(const float* __restrict__ dt_b)
{
  int idx = blockIdx.x*256 + threadIdx.x;
  if (idx >= NTOK*DI) return;
  int d = idx % DI;
  int t = idx / DI;
  const float* row = g_dbl + (size_t)t*DBL_W;
  float acc = dt_b[d];
  #pragma unroll
  for (int r=0;r<RRANK;++r)
    acc = fmaf(__ldg(row + r), g_dtwT[r*DI + d], acc);
  g_dt[idx] = softplusf(acc);
}

// ---------------- selective scan ----------------
__global__ void __launch_bounds__(128)
scan_kernel(const float* __restrict__ Dp)
{
  int gid = (blockIdx.x * 128 + threadIdx.x) >> 4;
  int n   = threadIdx.x & 15;
  int b   = gid / DI;
  int d   = gid - b*DI;
  float Aval = g_A[d*NST + n];
  float dpv  = Dp[d];
  float h = 0.f;
  const float*    __restrict__ dtp = g_dt  + (size_t)(b<<10)*DI + d;
  const unsigned* __restrict__ xcp = g_xc  + (size_t)(b<<10)*DI + d;
  const unsigned* __restrict__ zp  = g_xz  + (size_t)(b<<10)*768 + 384 + d;
  const float*    __restrict__ blp = g_dbl + (size_t)(b<<10)*DBL_W;
  unsigned* __restrict__ yp = g_y + (size_t)(b<<10)*DI + d;

  #pragma unroll 4
  for (int l = 0; l < LSEQ; ++l){
    float dtv = dtp[(size_t)l*DI];
    float xcv = unpackf(xcp[(size_t)l*DI]);
    float Bv  = blp[(size_t)l*DBL_W + RRANK + n];
    float Cv  = blp[(size_t)l*DBL_W + RRANK + NST + n];
    float dA  = __expf(dtv * Aval);
    h = fmaf(dA, h, dtv*Bv*xcv);
    float p = h * Cv;
    p += __shfl_xor_sync(0xffffffffu, p, 8, 16);
    p += __shfl_xor_sync(0xffffffffu, p, 4, 16);
    p += __shfl_xor_sync(0xffffffffu, p, 2, 16);
    p += __shfl_xor_sync(0xffffffffu, p, 1, 16);
    if (n == 0){
      float zv = unpackf(zp[(size_t)l*768]);
      yp[(size_t)l*DI] = packf((p + xcv*dpv) * siluf(zv));
    }
  }
}

// ---------------- host launcher ----------------
extern "C" void kernel_launch(void* const* d_in, const int* in_sizes, int n_in,
                              void* d_out, int out_size)
{
  (void)in_sizes; (void)n_in; (void)out_size;
  const float* x    = (const float*)d_in[0];
  const float* w1   = (const float*)d_in[1];
  const float* g1   = (const float*)d_in[2];
  const float* b1   = (const float*)d_in[3];
  const float* m1   = (const float*)d_in[4];
  const float* v1   = (const float*)d_in[5];
  const float* w2   = (const float*)d_in[6];
  const float* g2   = (const float*)d_in[7];
  const float* b2   = (const float*)d_in[8];
  const float* m2   = (const float*)d_in[9];
  const float* v2   = (const float*)d_in[10];
  const float* in_w = (const float*)d_in[11];
  const float* cw   = (const float*)d_in[12];
  const float* cb   = (const float*)d_in[13];
  const float* xp_w = (const float*)d_in[14];
  const float* dt_w = (const float*)d_in[15];
  const float* dt_b = (const float*)d_in[16];
  const float* A_log= (const float*)d_in[17];
  const float* Dp   = (const float*)d_in[18];
  const float* out_w= (const float*)d_in[19];
  const float* w3   = (const float*)d_in[20];
  const float* g3   = (const float*)d_in[21];
  const float* b3   = (const float*)d_in[22];
  const float* m3   = (const float*)d_in[23];
  const float* v3   = (const float*)d_in[24];
  const float* w4   = (const float*)d_in[25];
  const float* g4   = (const float*)d_in[26];
  const float* b4   = (const float*)d_in[27];
  const float* m4   = (const float*)d_in[28];
  const float* v4   = (const float*)d_in[29];

  unsigned *p_xt,*p_t1,*p_t2,*p_xz,*p_xc,*p_y,*p_t3,*p_t4,*p_w1t,*p_w4t;
  unsigned *p_w2p,*p_inwp,*p_xpwp,*p_outwp,*p_w3p;
  float *p_dbl,*p_bns,*p_bnb;
  cudaGetSymbolAddress((void**)&p_xt , g_xt );
  cudaGetSymbolAddress((void**)&p_t1 , g_t1 );
  cudaGetSymbolAddress((void**)&p_t2 , g_t2 );
  cudaGetSymbolAddress((void**)&p_xz , g_xz );
  cudaGetSymbolAddress((void**)&p_xc , g_xc );
  cudaGetSymbolAddress((void**)&p_y  , g_y  );
  cudaGetSymbolAddress((void**)&p_t3 , g_t3 );
  cudaGetSymbolAddress((void**)&p_t4 , g_t4 );
  cudaGetSymbolAddress((void**)&p_w1t, g_w1t);
  cudaGetSymbolAddress((void**)&p_w4t, g_w4t);
  cudaGetSymbolAddress((void**)&p_w2p, g_w2p);
  cudaGetSymbolAddress((void**)&p_inwp, g_inwp);
  cudaGetSymbolAddress((void**)&p_xpwp, g_xpwp);
  cudaGetSymbolAddress((void**)&p_outwp, g_outwp);
  cudaGetSymbolAddress((void**)&p_w3p, g_w3p);
  cudaGetSymbolAddress((void**)&p_dbl, g_dbl);
  cudaGetSymbolAddress((void**)&p_bns, g_bns);
  cudaGetSymbolAddress((void**)&p_bnb, g_bnb);

  // conv1 at my 0-based launch #3 (ncu-captured slot)
  prep_kernel<<<24,256>>>(g1,b1,m1,v1, g2,b2,m2,v2, g3,b3,m3,v3, g4,b4,m4,v4, A_log, dt_w); // #0
  transpose_in<<<dim3(3,32,8), dim3(32,8)>>>(x, p_xt);                                       // #1
  prep_weights<<<(PW_TOTAL+255)/256,256>>>(w1, w4, w2, in_w, xp_w, out_w, w3);               // #2
  conv3x3_gemm<1,false><<<dim3(NTOK/BM, 2),256>>>(p_xt, p_w1t, p_t1, D_IN, D_IN, p_bns+0, p_bnb+0); // #3

  gemm_nt<2,true><<<dim3(NTOK/BM, 3),256>>>(p_t1, D_IN, p_w2p, p_t2, D_MID, D_IN, p_bns+192, p_bnb+192);
  gemm_nt<0,true><<<dim3(NTOK/BM, 12),256>>>(p_t2, D_MID, p_inwp, p_xz, 768, D_MID, nullptr, nullptr);
  dwconv_silu<<<(NTOK*DI)/256,256>>>(cw, cb);
  gemm_nt<0,false><<<dim3(NTOK/BM, 1),256>>>(p_xc, DI, p_xpwp, p_dbl, DBL_W, DI, nullptr, nullptr);
  dtproj_kernel<<<(NTOK*DI)/256,256>>>(dt_b);
  scan_kernel<<<(NTOK/LSEQ)*DI*16/128,128>>>(Dp);
  gemm_nt<0,true><<<dim3(NTOK/BM, 3),256>>>(p_y, DI, p_outwp, p_t3, D_MID, DI, nullptr, nullptr);
  gemm_nt<2,true><<<dim3(NTOK/BM, 3),256>>>(p_t3, D_MID, p_w3p, p_t4, D_MID, D_MID, p_bns+384, p_bnb+384);
  conv3x3_gemm<1,true><<<dim3(NTOK/BM, 3),256>>>(p_t4, p_w4t, (float*)d_out, D_MID, D_MID, p_bns+576, p_bnb+576);
}